// round 3
// baseline (speedup 1.0000x reference)
#include <cuda_runtime.h>
#include <math.h>
#include <stdint.h>

#define BATCH 16
#define SEQ   1024
#define DMODEL 512
#define NHEAD 4
#define HDIM  128
#define MROWS (BATCH * SEQ)   // 16384
#define DMLP  1024

// ---------------- scratch (device globals; no allocation allowed) ----------
__device__ float g_x1n [MROWS * DMODEL];
__device__ float g_x2n [MROWS * DMODEL];
__device__ float g_q   [MROWS * DMODEL];
__device__ float g_k   [MROWS * DMODEL];
__device__ float g_v   [MROWS * DMODEL];
__device__ float g_ctx [MROWS * DMODEL];
__device__ float g_src1[MROWS * DMODEL];
__device__ float g_src2[MROWS * DMODEL];
__device__ float g_xres[MROWS * DMODEL];
__device__ float g_h   [MROWS * DMLP];

// ---------------- tf32 helpers ---------------------------------------------
__device__ __forceinline__ uint32_t f2tf(float f) {
    uint32_t u;
    asm("cvt.rna.tf32.f32 %0, %1;" : "=r"(u) : "f"(f));
    return u;
}

__device__ __forceinline__ void mma_tf32(float* c, const uint32_t* a, const uint32_t* b) {
    asm volatile(
        "mma.sync.aligned.m16n8k8.row.col.f32.tf32.tf32.f32 "
        "{%0,%1,%2,%3}, {%4,%5,%6,%7}, {%8,%9}, {%0,%1,%2,%3};"
        : "+f"(c[0]), "+f"(c[1]), "+f"(c[2]), "+f"(c[3])
        : "r"(a[0]), "r"(a[1]), "r"(a[2]), "r"(a[3]),
          "r"(b[0]), "r"(b[1]));
}

// ---------------- LayerNorm: one block (128 thr) per row of 512 ------------
__global__ void ln_kernel(const float* __restrict__ x,
                          const float* __restrict__ g,
                          const float* __restrict__ b,
                          float* __restrict__ y) {
    int row = blockIdx.x;
    const float* xr = x + (size_t)row * DMODEL;
    float*       yr = y + (size_t)row * DMODEL;
    int t = threadIdx.x;
    float4 v4 = ((const float4*)xr)[t];

    __shared__ float red[4];
    float s = v4.x + v4.y + v4.z + v4.w;
    #pragma unroll
    for (int o = 16; o; o >>= 1) s += __shfl_xor_sync(0xffffffffu, s, o);
    if ((t & 31) == 0) red[t >> 5] = s;
    __syncthreads();
    float mean = (red[0] + red[1] + red[2] + red[3]) * (1.0f / DMODEL);
    __syncthreads();

    float dx = v4.x - mean, dy = v4.y - mean, dz = v4.z - mean, dw = v4.w - mean;
    float vs = dx*dx + dy*dy + dz*dz + dw*dw;
    #pragma unroll
    for (int o = 16; o; o >>= 1) vs += __shfl_xor_sync(0xffffffffu, vs, o);
    if ((t & 31) == 0) red[t >> 5] = vs;
    __syncthreads();
    float var = (red[0] + red[1] + red[2] + red[3]) * (1.0f / DMODEL);
    float inv = rsqrtf(var + 1e-6f);

    float4 g4 = ((const float4*)g)[t];
    float4 b4 = ((const float4*)b)[t];
    float4 o4;
    o4.x = dx * inv * g4.x + b4.x;
    o4.y = dy * inv * g4.y + b4.y;
    o4.z = dz * inv * g4.z + b4.z;
    o4.w = dw * inv * g4.w + b4.w;
    ((float4*)yr)[t] = o4;
}

// ---------------- tf32 tensor-core GEMM ------------------------------------
// C = A[M,K] @ W[K,N] + bias (+resid)(+gelu)
// Block: 256 thr, tile 128(M) x 128(N), K-step 32.
// Warps: 8, grid 2(M) x 4(N); each warp 64x32 via 4x4 m16n8k8 frags.
#define ACT_NONE 0
#define ACT_GELU 1

__global__ __launch_bounds__(256, 2)
void gemm_tc(const float* __restrict__ A, const float* __restrict__ W,
             const float* __restrict__ bias, const float* __restrict__ resid,
             float* __restrict__ C, int M, int N, int K, int act) {
    // A row-major tile: pitch 36 (== 4 mod 32 -> conflict-free a-frags)
    // B row-major tile: pitch 136 (== 8 mod 32 -> conflict-free b-frags)
    __shared__ uint32_t As[128][36];
    __shared__ uint32_t Bs[32][136];

    int tid = threadIdx.x, lane = tid & 31, wid = tid >> 5;
    int m0 = blockIdx.y * 128, n0 = blockIdx.x * 128;
    int wm = (wid & 1) * 64, wn = (wid >> 1) * 32;

    float acc[4][4][4];
    #pragma unroll
    for (int i = 0; i < 4; i++)
        #pragma unroll
        for (int j = 0; j < 4; j++)
            #pragma unroll
            for (int k = 0; k < 4; k++) acc[i][j][k] = 0.f;

    int am = tid >> 3;            // 0..31 (A row within group)
    int ak = (tid & 7) * 4;       // 0..28 (A k-col)
    int bn = (tid & 31) * 4;      // 0..124 (B n-col)
    int bk = tid >> 5;            // 0..7  (B k-row)

    for (int k0 = 0; k0 < K; k0 += 32) {
        #pragma unroll
        for (int i = 0; i < 4; i++) {
            float4 v = *(const float4*)&A[(size_t)(m0 + am + i * 32) * K + k0 + ak];
            uint32_t* d = &As[am + i * 32][ak];
            d[0] = f2tf(v.x); d[1] = f2tf(v.y); d[2] = f2tf(v.z); d[3] = f2tf(v.w);
        }
        #pragma unroll
        for (int i = 0; i < 4; i++) {
            float4 v = *(const float4*)&W[(size_t)(k0 + bk + i * 8) * N + n0 + bn];
            uint32_t* d = &Bs[bk + i * 8][bn];
            d[0] = f2tf(v.x); d[1] = f2tf(v.y); d[2] = f2tf(v.z); d[3] = f2tf(v.w);
        }
        __syncthreads();

        int r4 = lane >> 2, c4 = lane & 3;
        #pragma unroll
        for (int ks = 0; ks < 4; ks++) {
            int kk = ks * 8 + c4;
            uint32_t a[4][4], b[4][2];
            #pragma unroll
            for (int mf = 0; mf < 4; mf++) {
                int m = wm + mf * 16 + r4;
                a[mf][0] = As[m][kk];
                a[mf][1] = As[m + 8][kk];
                a[mf][2] = As[m][kk + 4];
                a[mf][3] = As[m + 8][kk + 4];
            }
            #pragma unroll
            for (int nf = 0; nf < 4; nf++) {
                int n = wn + nf * 8 + r4;
                b[nf][0] = Bs[kk][n];
                b[nf][1] = Bs[kk + 4][n];
            }
            #pragma unroll
            for (int mf = 0; mf < 4; mf++)
                #pragma unroll
                for (int nf = 0; nf < 4; nf++)
                    mma_tf32(acc[mf][nf], a[mf], b[nf]);
        }
        __syncthreads();
    }

    // epilogue
    int r4 = lane >> 2, c2 = (lane & 3) * 2;
    #pragma unroll
    for (int mf = 0; mf < 4; mf++) {
        #pragma unroll
        for (int nf = 0; nf < 4; nf++) {
            int row = m0 + wm + mf * 16 + r4;
            int col = n0 + wn + nf * 8 + c2;
            float2 bi = *(const float2*)&bias[col];
            #pragma unroll
            for (int hh = 0; hh < 2; hh++) {
                int r = row + hh * 8;
                float v0 = acc[mf][nf][hh * 2 + 0] + bi.x;
                float v1 = acc[mf][nf][hh * 2 + 1] + bi.y;
                if (resid) {
                    float2 rr = *(const float2*)&resid[(size_t)r * N + col];
                    v0 += rr.x; v1 += rr.y;
                }
                if (act == ACT_GELU) {
                    v0 = 0.5f * v0 * (1.0f + erff(v0 * 0.70710678118654752f));
                    v1 = 0.5f * v1 * (1.0f + erff(v1 * 0.70710678118654752f));
                }
                float2 o2 = make_float2(v0, v1);
                *(float2*)&C[(size_t)r * N + col] = o2;
            }
        }
    }
}

// ---------------- tf32 tensor-core flash attention -------------------------
// grid (SEQ/128, NHEAD, BATCH), 256 thr (8 warps). Each warp owns 16 q rows.
// K chunks of 64. Q,K,V,P all row-major SMEM, pitches chosen conflict-free.
#define ATT_QW (128 * 132)
#define ATT_KW (64 * 132)
#define ATT_VW (64 * 136)
#define ATT_PW (128 * 68)
#define ATT_SMEM_BYTES ((ATT_QW + ATT_KW + ATT_VW + ATT_PW) * 4)

__global__ __launch_bounds__(256, 1)
void attn_tc(const float* __restrict__ Q, const float* __restrict__ K,
             const float* __restrict__ V, float* __restrict__ O) {
    extern __shared__ uint32_t sm[];
    uint32_t* Qs = sm;                  // [128][132]  q-rows x hd
    uint32_t* Ks = Qs + ATT_QW;         // [64][132]   keys  x hd
    uint32_t* Vs = Ks + ATT_KW;         // [64][136]   keys  x hd
    uint32_t* Ps = Vs + ATT_VW;         // [128][68]   q-rows x keys

    int tid = threadIdx.x, lane = tid & 31, wid = tid >> 5;
    int q0 = blockIdx.x * 128, h = blockIdx.y, b = blockIdx.z;
    size_t gq = ((size_t)b * SEQ + q0) * DMODEL + (size_t)h * HDIM;
    const float scale = 0.08838834764831845f;  // 1/sqrt(128)

    int d4 = lane * 4;        // 0..124
    int rr = tid >> 5;        // warp id = row group

    // stage Q (scaled) once
    #pragma unroll
    for (int i = 0; i < 16; i++) {
        int qq = rr + i * 8;
        float4 v = *(const float4*)&Q[gq + (size_t)qq * DMODEL + d4];
        uint32_t* d = &Qs[qq * 132 + d4];
        d[0] = f2tf(v.x * scale); d[1] = f2tf(v.y * scale);
        d[2] = f2tf(v.z * scale); d[3] = f2tf(v.w * scale);
    }

    float mrow[2] = {-1e30f, -1e30f}, lrow[2] = {0.f, 0.f};
    float o[16][4];
    #pragma unroll
    for (int i = 0; i < 16; i++)
        #pragma unroll
        for (int j = 0; j < 4; j++) o[i][j] = 0.f;

    int r4 = lane >> 2, c4 = lane & 3;
    int mq = wid * 16 + r4;

    for (int kc = 0; kc < SEQ; kc += 64) {
        __syncthreads();
        size_t gk = ((size_t)b * SEQ + kc) * DMODEL + (size_t)h * HDIM;
        #pragma unroll
        for (int i = 0; i < 8; i++) {
            int kr = rr + i * 8;
            float4 kv = *(const float4*)&K[gk + (size_t)kr * DMODEL + d4];
            float4 vv = *(const float4*)&V[gk + (size_t)kr * DMODEL + d4];
            uint32_t* dk = &Ks[kr * 132 + d4];
            dk[0] = f2tf(kv.x); dk[1] = f2tf(kv.y); dk[2] = f2tf(kv.z); dk[3] = f2tf(kv.w);
            uint32_t* dv = &Vs[kr * 136 + d4];
            dv[0] = f2tf(vv.x); dv[1] = f2tf(vv.y); dv[2] = f2tf(vv.z); dv[3] = f2tf(vv.w);
        }
        __syncthreads();

        // S = Q @ K^T : warp computes 16 x 64
        float s[8][4];
        #pragma unroll
        for (int nf = 0; nf < 8; nf++)
            #pragma unroll
            for (int j = 0; j < 4; j++) s[nf][j] = 0.f;

        #pragma unroll
        for (int ks = 0; ks < 16; ks++) {
            int kk = ks * 8 + c4;
            uint32_t a[4];
            a[0] = Qs[mq * 132 + kk];
            a[1] = Qs[(mq + 8) * 132 + kk];
            a[2] = Qs[mq * 132 + kk + 4];
            a[3] = Qs[(mq + 8) * 132 + kk + 4];
            #pragma unroll
            for (int nf = 0; nf < 8; nf++) {
                int n = nf * 8 + r4;
                uint32_t bb[2];
                bb[0] = Ks[n * 132 + kk];       // B[k][n] = K[key=n][d=k]
                bb[1] = Ks[n * 132 + kk + 4];
                mma_tf32(s[nf], a, bb);
            }
        }

        // online softmax per row-half
        #pragma unroll
        for (int h2 = 0; h2 < 2; h2++) {
            int base = h2 * 2;
            float mx = -1e30f;
            #pragma unroll
            for (int nf = 0; nf < 8; nf++)
                mx = fmaxf(mx, fmaxf(s[nf][base], s[nf][base + 1]));
            mx = fmaxf(mx, __shfl_xor_sync(0xffffffffu, mx, 1));
            mx = fmaxf(mx, __shfl_xor_sync(0xffffffffu, mx, 2));
            float mnew = fmaxf(mrow[h2], mx);
            float corr = __expf(mrow[h2] - mnew);
            mrow[h2] = mnew;

            int qrow = mq + 8 * h2;
            float ps = 0.f;
            #pragma unroll
            for (int nf = 0; nf < 8; nf++) {
                float p0 = __expf(s[nf][base]     - mnew);
                float p1 = __expf(s[nf][base + 1] - mnew);
                ps += p0 + p1;
                int key = nf * 8 + 2 * c4;
                Ps[qrow * 68 + key]     = f2tf(p0);
                Ps[qrow * 68 + key + 1] = f2tf(p1);
            }
            ps += __shfl_xor_sync(0xffffffffu, ps, 1);
            ps += __shfl_xor_sync(0xffffffffu, ps, 2);
            lrow[h2] = lrow[h2] * corr + ps;
            #pragma unroll
            for (int nf = 0; nf < 16; nf++) {
                o[nf][base]     *= corr;
                o[nf][base + 1] *= corr;
            }
        }
        __syncwarp();

        // O += P @ V : warp 16 x 128, K = 64 keys
        #pragma unroll
        for (int ks = 0; ks < 8; ks++) {
            int kk = ks * 8 + c4;
            uint32_t a[4];
            a[0] = Ps[mq * 68 + kk];
            a[1] = Ps[(mq + 8) * 68 + kk];
            a[2] = Ps[mq * 68 + kk + 4];
            a[3] = Ps[(mq + 8) * 68 + kk + 4];
            #pragma unroll
            for (int nf = 0; nf < 16; nf++) {
                int n = nf * 8 + r4;
                uint32_t bb[2];
                bb[0] = Vs[kk * 136 + n];
                bb[1] = Vs[(kk + 4) * 136 + n];
                mma_tf32(o[nf], a, bb);
            }
        }
    }

    float inv0 = 1.0f / lrow[0], inv1 = 1.0f / lrow[1];
    #pragma unroll
    for (int nf = 0; nf < 16; nf++) {
        int col = nf * 8 + 2 * c4;
        size_t base0 = gq + (size_t)mq * DMODEL + col;
        float2 o0 = make_float2(o[nf][0] * inv0, o[nf][1] * inv0);
        float2 o1 = make_float2(o[nf][2] * inv1, o[nf][3] * inv1);
        *(float2*)&O[base0]                 = o0;
        *(float2*)&O[base0 + 8 * DMODEL]    = o1;
    }
}

// ---------------- driver ----------------------------------------------------
extern "C" void kernel_launch(void* const* d_in, const int* in_sizes, int n_in,
                              void* d_out, int out_size) {
    const float* x1    = (const float*)d_in[0];
    const float* x2    = (const float*)d_in[1];
    const float* ln1_g = (const float*)d_in[2];
    const float* ln1_b = (const float*)d_in[3];
    const float* ln2_g = (const float*)d_in[4];
    const float* ln2_b = (const float*)d_in[5];
    const float* lnf_g = (const float*)d_in[6];
    const float* lnf_b = (const float*)d_in[7];
    const float* Wq1  = (const float*)d_in[8];   const float* bq1  = (const float*)d_in[9];
    const float* Wk1  = (const float*)d_in[10];  const float* bk1  = (const float*)d_in[11];
    const float* Wv1  = (const float*)d_in[12];  const float* bv1  = (const float*)d_in[13];
    const float* Wq2  = (const float*)d_in[14];  const float* bq2  = (const float*)d_in[15];
    const float* Wk2  = (const float*)d_in[16];  const float* bk2  = (const float*)d_in[17];
    const float* Wv2  = (const float*)d_in[18];  const float* bv2  = (const float*)d_in[19];
    const float* Wq12 = (const float*)d_in[20];  const float* bq12 = (const float*)d_in[21];
    const float* Wk12 = (const float*)d_in[22];  const float* bk12 = (const float*)d_in[23];
    const float* Wv12 = (const float*)d_in[24];  const float* bv12 = (const float*)d_in[25];
    const float* Wo   = (const float*)d_in[26];  const float* bo   = (const float*)d_in[27];
    const float* W1   = (const float*)d_in[28];  const float* b1   = (const float*)d_in[29];
    const float* W2   = (const float*)d_in[30];  const float* b2   = (const float*)d_in[31];
    float* out = (float*)d_out;

    float *x1n, *x2n, *q, *k, *v, *ctx, *src1, *src2, *xres, *hbuf;
    cudaGetSymbolAddress((void**)&x1n,  g_x1n);
    cudaGetSymbolAddress((void**)&x2n,  g_x2n);
    cudaGetSymbolAddress((void**)&q,    g_q);
    cudaGetSymbolAddress((void**)&k,    g_k);
    cudaGetSymbolAddress((void**)&v,    g_v);
    cudaGetSymbolAddress((void**)&ctx,  g_ctx);
    cudaGetSymbolAddress((void**)&src1, g_src1);
    cudaGetSymbolAddress((void**)&src2, g_src2);
    cudaGetSymbolAddress((void**)&xres, g_xres);
    cudaGetSymbolAddress((void**)&hbuf, g_h);

    cudaFuncSetAttribute(attn_tc, cudaFuncAttributeMaxDynamicSharedMemorySize,
                         ATT_SMEM_BYTES);

    dim3 gAttn(SEQ / 128, NHEAD, BATCH);
    dim3 g512 (DMODEL / 128, MROWS / 128);   // (4, 128)
    dim3 g1024(DMLP   / 128, MROWS / 128);   // (8, 128)

    // normalize both streams
    ln_kernel<<<MROWS, 128>>>(x1, ln1_g, ln1_b, x1n);
    ln_kernel<<<MROWS, 128>>>(x2, ln2_g, ln2_b, x2n);

    // stream-1 self-attention
    gemm_tc<<<g512, 256>>>(x1n, Wq1, bq1, nullptr, q, MROWS, DMODEL, DMODEL, ACT_NONE);
    gemm_tc<<<g512, 256>>>(x1n, Wk1, bk1, nullptr, k, MROWS, DMODEL, DMODEL, ACT_NONE);
    gemm_tc<<<g512, 256>>>(x1n, Wv1, bv1, nullptr, v, MROWS, DMODEL, DMODEL, ACT_NONE);
    attn_tc<<<gAttn, 256, ATT_SMEM_BYTES>>>(q, k, v, ctx);
    gemm_tc<<<g512, 256>>>(ctx, Wo, bo, x1n, src1, MROWS, DMODEL, DMODEL, ACT_NONE);

    // stream-2 self-attention
    gemm_tc<<<g512, 256>>>(x2n, Wq2, bq2, nullptr, q, MROWS, DMODEL, DMODEL, ACT_NONE);
    gemm_tc<<<g512, 256>>>(x2n, Wk2, bk2, nullptr, k, MROWS, DMODEL, DMODEL, ACT_NONE);
    gemm_tc<<<g512, 256>>>(x2n, Wv2, bv2, nullptr, v, MROWS, DMODEL, DMODEL, ACT_NONE);
    attn_tc<<<gAttn, 256, ATT_SMEM_BYTES>>>(q, k, v, ctx);
    gemm_tc<<<g512, 256>>>(ctx, Wo, bo, x2n, src2, MROWS, DMODEL, DMODEL, ACT_NONE);

    // cross attention: Q from src1, K/V from src2
    gemm_tc<<<g512, 256>>>(src1, Wq12, bq12, nullptr, q, MROWS, DMODEL, DMODEL, ACT_NONE);
    gemm_tc<<<g512, 256>>>(src2, Wk12, bk12, nullptr, k, MROWS, DMODEL, DMODEL, ACT_NONE);
    gemm_tc<<<g512, 256>>>(src2, Wv12, bv12, nullptr, v, MROWS, DMODEL, DMODEL, ACT_NONE);
    attn_tc<<<gAttn, 256, ATT_SMEM_BYTES>>>(q, k, v, ctx);
    gemm_tc<<<g512, 256>>>(ctx, Wo, bo, x1, xres, MROWS, DMODEL, DMODEL, ACT_NONE);

    // final LN + MLP; out = x + gelu(h@W1+b1)@W2+b2
    ln_kernel<<<MROWS, 128>>>(xres, lnf_g, lnf_b, x1n);
    gemm_tc<<<g1024, 256>>>(x1n, W1, b1, nullptr, hbuf, MROWS, DMLP, DMODEL, ACT_GELU);
    gemm_tc<<<g512, 256>>>(hbuf, W2, b2, xres, out, MROWS, DMODEL, DMLP, ACT_NONE);
}

// round 4
// speedup vs baseline: 1.1710x; 1.1710x over previous
#include <cuda_runtime.h>
#include <math.h>
#include <stdint.h>

#define BATCH 16
#define SEQ   1024
#define DMODEL 512
#define NHEAD 4
#define HDIM  128
#define MROWS (BATCH * SEQ)
#define DMLP  1024

__device__ float g_x1n [MROWS * DMODEL];
__device__ float g_x2n [MROWS * DMODEL];
__device__ float g_q   [MROWS * DMODEL];
__device__ float g_k   [MROWS * DMODEL];
__device__ float g_v   [MROWS * DMODEL];
__device__ float g_ctx [MROWS * DMODEL];
__device__ float g_src1[MROWS * DMODEL];
__device__ float g_src2[MROWS * DMODEL];
__device__ float g_xres[MROWS * DMODEL];
__device__ float g_h   [MROWS * DMLP];
__device__ float g_wr  [10 * DMODEL * DMODEL + 2 * DMODEL * DMLP];

__device__ __forceinline__ uint32_t f2tf(float f) {
    uint32_t u; asm("cvt.rna.tf32.f32 %0, %1;" : "=r"(u) : "f"(f)); return u;
}
__device__ __forceinline__ float roundtf(float f) { return __uint_as_float(f2tf(f)); }
__device__ __forceinline__ void mma_tf32(float* c, const uint32_t* a, const uint32_t* b) {
    asm volatile(
        "mma.sync.aligned.m16n8k8.row.col.f32.tf32.tf32.f32 "
        "{%0,%1,%2,%3}, {%4,%5,%6,%7}, {%8,%9}, {%0,%1,%2,%3};"
        : "+f"(c[0]), "+f"(c[1]), "+f"(c[2]), "+f"(c[3])
        : "r"(a[0]), "r"(a[1]), "r"(a[2]), "r"(a[3]), "r"(b[0]), "r"(b[1]));
}
__device__ __forceinline__ uint32_t s2u(const void* p) {
    return (uint32_t)__cvta_generic_to_shared(p);
}
__device__ __forceinline__ void cpa16(uint32_t dst, const float* src) {
    asm volatile("cp.async.cg.shared.global [%0], [%1], 16;" :: "r"(dst), "l"(src));
}
#define CP_COMMIT() asm volatile("cp.async.commit_group;")
template <int N> __device__ __forceinline__ void cp_wait() {
    asm volatile("cp.async.wait_group %0;" :: "n"(N));
}

// -------- weight pre-round ---------------------------------------------------
struct WPtrs { const float* s[12]; };
__global__ void round_w(WPtrs p, float* dst) {
    int i4 = blockIdx.x * blockDim.x + threadIdx.x;
    const int N4 = (10 * 262144 + 2 * 524288) / 4;
    if (i4 >= N4) return;
    int idx = i4 * 4, a, off;
    if (idx < 2621440) { a = idx >> 18; off = idx & 262143; }
    else { int r = idx - 2621440; a = 10 + (r >> 19); off = r & 524287; }
    float4 v = *(const float4*)&p.s[a][off];
    v.x = roundtf(v.x); v.y = roundtf(v.y); v.z = roundtf(v.z); v.w = roundtf(v.w);
    *(float4*)&dst[idx] = v;
}

// -------- LayerNorm (rounds output to tf32) ----------------------------------
__global__ void ln_kernel(const float* __restrict__ x, const float* __restrict__ g,
                          const float* __restrict__ b, float* __restrict__ y) {
    int row = blockIdx.x, t = threadIdx.x;
    const float* xr = x + (size_t)row * DMODEL;
    float* yr = y + (size_t)row * DMODEL;
    float4 v4 = ((const float4*)xr)[t];
    __shared__ float red[4];
    float s = v4.x + v4.y + v4.z + v4.w;
    #pragma unroll
    for (int o = 16; o; o >>= 1) s += __shfl_xor_sync(0xffffffffu, s, o);
    if ((t & 31) == 0) red[t >> 5] = s;
    __syncthreads();
    float mean = (red[0] + red[1] + red[2] + red[3]) * (1.0f / DMODEL);
    __syncthreads();
    float dx = v4.x - mean, dy = v4.y - mean, dz = v4.z - mean, dw = v4.w - mean;
    float vs = dx*dx + dy*dy + dz*dz + dw*dw;
    #pragma unroll
    for (int o = 16; o; o >>= 1) vs += __shfl_xor_sync(0xffffffffu, vs, o);
    if ((t & 31) == 0) red[t >> 5] = vs;
    __syncthreads();
    float var = (red[0] + red[1] + red[2] + red[3]) * (1.0f / DMODEL);
    float inv = rsqrtf(var + 1e-6f);
    float4 g4 = ((const float4*)g)[t];
    float4 b4 = ((const float4*)b)[t];
    float4 o4;
    o4.x = roundtf(dx * inv * g4.x + b4.x);
    o4.y = roundtf(dy * inv * g4.y + b4.y);
    o4.z = roundtf(dz * inv * g4.z + b4.z);
    o4.w = roundtf(dw * inv * g4.w + b4.w);
    ((float4*)yr)[t] = o4;
}

// -------- tf32 GEMM, cp.async double-buffered --------------------------------
#define FLAG_GELU  1
#define FLAG_ROUND 2
#define GA (128 * 36)
#define GB (32 * 136)
#define GEMM_SMEM (2 * (GA + GB) * 4)

__global__ __launch_bounds__(256, 2)
void gemm_tc(const float* __restrict__ A, const float* __restrict__ W,
             const float* __restrict__ bias, const float* __restrict__ resid,
             float* __restrict__ C, int M, int N, int K, int flags, float oscale) {
    extern __shared__ uint32_t smem[];
    uint32_t* As = smem;           // [2][128][36]
    uint32_t* Bs = smem + 2 * GA;  // [2][32][136]
    int tid = threadIdx.x, lane = tid & 31, wid = tid >> 5;
    int m0 = blockIdx.y * 128, n0 = blockIdx.x * 128;
    int wm = (wid & 1) * 64, wn = (wid >> 1) * 32;

    float acc[4][4][4];
    #pragma unroll
    for (int i = 0; i < 4; i++)
        #pragma unroll
        for (int j = 0; j < 4; j++)
            #pragma unroll
            for (int k = 0; k < 4; k++) acc[i][j][k] = 0.f;

    int arow = tid >> 3, acol = (tid & 7) * 4;
    int brow = tid >> 5, bcol = (tid & 31) * 4;

    auto stage = [&](int buf, int k0) {
        #pragma unroll
        for (int i = 0; i < 4; i++) {
            int row = arow + 32 * i;
            cpa16(s2u(&As[buf * GA + row * 36 + acol]),
                  &A[(size_t)(m0 + row) * K + k0 + acol]);
        }
        #pragma unroll
        for (int i = 0; i < 4; i++) {
            int row = brow + 8 * i;
            cpa16(s2u(&Bs[buf * GB + row * 136 + bcol]),
                  &W[(size_t)(k0 + row) * N + n0 + bcol]);
        }
        CP_COMMIT();
    };

    stage(0, 0);
    int T = K >> 5, r4 = lane >> 2, c4 = lane & 3;

    for (int it = 0; it < T; it++) {
        cp_wait<0>();
        __syncthreads();
        if (it + 1 < T) stage((it + 1) & 1, (it + 1) * 32);
        const uint32_t* Ab = &As[(it & 1) * GA];
        const uint32_t* Bb = &Bs[(it & 1) * GB];
        #pragma unroll
        for (int ks = 0; ks < 4; ks++) {
            int kk = ks * 8 + c4;
            uint32_t a[4][4], b[4][2];
            #pragma unroll
            for (int mf = 0; mf < 4; mf++) {
                int m = wm + mf * 16 + r4;
                a[mf][0] = Ab[m * 36 + kk];
                a[mf][1] = Ab[(m + 8) * 36 + kk];
                a[mf][2] = Ab[m * 36 + kk + 4];
                a[mf][3] = Ab[(m + 8) * 36 + kk + 4];
            }
            #pragma unroll
            for (int nf = 0; nf < 4; nf++) {
                int n = wn + nf * 8 + r4;
                b[nf][0] = Bb[kk * 136 + n];
                b[nf][1] = Bb[(kk + 4) * 136 + n];
            }
            #pragma unroll
            for (int mf = 0; mf < 4; mf++)
                #pragma unroll
                for (int nf = 0; nf < 4; nf++)
                    mma_tf32(acc[mf][nf], a[mf], b[nf]);
        }
        __syncthreads();
    }

    int c2 = (lane & 3) * 2;
    #pragma unroll
    for (int mf = 0; mf < 4; mf++) {
        #pragma unroll
        for (int nf = 0; nf < 4; nf++) {
            int row = m0 + wm + mf * 16 + r4;
            int col = n0 + wn + nf * 8 + c2;
            float2 bi = *(const float2*)&bias[col];
            #pragma unroll
            for (int hh = 0; hh < 2; hh++) {
                int r = row + hh * 8;
                float v0 = acc[mf][nf][hh * 2 + 0] + bi.x;
                float v1 = acc[mf][nf][hh * 2 + 1] + bi.y;
                if (resid) {
                    float2 rr = *(const float2*)&resid[(size_t)r * N + col];
                    v0 += rr.x; v1 += rr.y;
                }
                if (flags & FLAG_GELU) {
                    v0 = 0.5f * v0 * (1.0f + erff(v0 * 0.70710678118654752f));
                    v1 = 0.5f * v1 * (1.0f + erff(v1 * 0.70710678118654752f));
                }
                v0 *= oscale; v1 *= oscale;
                if (flags & FLAG_ROUND) { v0 = roundtf(v0); v1 = roundtf(v1); }
                *(float2*)&C[(size_t)r * N + col] = make_float2(v0, v1);
            }
        }
    }
}

// -------- tf32 flash attention, cp.async pipelined ---------------------------
#define AQ (128 * 132)
#define AK (64 * 132)
#define AV (64 * 136)
#define AP (128 * 68)
#define ATT_SMEM ((AQ + 2 * AK + AV + AP) * 4)
#define NIT (SEQ / 64)

__global__ __launch_bounds__(256, 1)
void attn_tc(const float* __restrict__ Q, const float* __restrict__ K,
             const float* __restrict__ V, float* __restrict__ O) {
    extern __shared__ uint32_t smem[];
    uint32_t* Qs = smem;
    uint32_t* Ks = Qs + AQ;         // [2][64][132]
    uint32_t* Vs = Ks + 2 * AK;     // [64][136]
    uint32_t* Ps = Vs + AV;         // [128][68]

    int tid = threadIdx.x, lane = tid & 31, wid = tid >> 5;
    int q0 = blockIdx.x * 128, h = blockIdx.y, b = blockIdx.z;
    size_t gq  = ((size_t)b * SEQ + q0) * DMODEL + (size_t)h * HDIM;
    size_t gk0 = ((size_t)b * SEQ) * DMODEL + (size_t)h * HDIM;
    int srow = tid >> 5, scol = (tid & 31) * 4;

    #pragma unroll
    for (int i = 0; i < 16; i++) {
        int row = srow + 8 * i;
        cpa16(s2u(&Qs[row * 132 + scol]), &Q[gq + (size_t)row * DMODEL + scol]);
    }
    CP_COMMIT();
    #pragma unroll
    for (int i = 0; i < 8; i++) {
        int row = srow + 8 * i;
        cpa16(s2u(&Ks[row * 132 + scol]), &K[gk0 + (size_t)row * DMODEL + scol]);
    }
    CP_COMMIT();
    #pragma unroll
    for (int i = 0; i < 8; i++) {
        int row = srow + 8 * i;
        cpa16(s2u(&Vs[row * 136 + scol]), &V[gk0 + (size_t)row * DMODEL + scol]);
    }
    CP_COMMIT();
    cp_wait<0>();
    __syncthreads();

    float mrow[2] = {-1e30f, -1e30f}, lrow[2] = {0.f, 0.f};
    float o[16][4];
    #pragma unroll
    for (int i = 0; i < 16; i++)
        #pragma unroll
        for (int j = 0; j < 4; j++) o[i][j] = 0.f;

    int r4 = lane >> 2, c4 = lane & 3;
    int mq = wid * 16 + r4;

    for (int ic = 0; ic < NIT; ic++) {
        if (ic > 0) { cp_wait<1>(); __syncthreads(); }   // K(ic) ready
        const uint32_t* Kb = &Ks[(ic & 1) * AK];

        if (ic + 1 < NIT) {                              // prefetch K(ic+1)
            size_t gk = gk0 + (size_t)(ic + 1) * 64 * DMODEL;
            #pragma unroll
            for (int i = 0; i < 8; i++) {
                int row = srow + 8 * i;
                cpa16(s2u(&Ks[((ic + 1) & 1) * AK + row * 132 + scol]),
                      &K[gk + (size_t)row * DMODEL + scol]);
            }
            CP_COMMIT();
        }

        float s[8][4];
        #pragma unroll
        for (int nf = 0; nf < 8; nf++)
            #pragma unroll
            for (int j = 0; j < 4; j++) s[nf][j] = 0.f;

        #pragma unroll
        for (int ks = 0; ks < 16; ks++) {
            int kk = ks * 8 + c4;
            uint32_t a[4];
            a[0] = Qs[mq * 132 + kk];
            a[1] = Qs[(mq + 8) * 132 + kk];
            a[2] = Qs[mq * 132 + kk + 4];
            a[3] = Qs[(mq + 8) * 132 + kk + 4];
            #pragma unroll
            for (int nf = 0; nf < 8; nf++) {
                int n = nf * 8 + r4;
                uint32_t bb[2];
                bb[0] = Kb[n * 132 + kk];
                bb[1] = Kb[n * 132 + kk + 4];
                mma_tf32(s[nf], a, bb);
            }
        }

        #pragma unroll
        for (int h2 = 0; h2 < 2; h2++) {
            int base = h2 * 2;
            float mx = -1e30f;
            #pragma unroll
            for (int nf = 0; nf < 8; nf++)
                mx = fmaxf(mx, fmaxf(s[nf][base], s[nf][base + 1]));
            mx = fmaxf(mx, __shfl_xor_sync(0xffffffffu, mx, 1));
            mx = fmaxf(mx, __shfl_xor_sync(0xffffffffu, mx, 2));
            float mnew = fmaxf(mrow[h2], mx);
            float corr = __expf(mrow[h2] - mnew);
            mrow[h2] = mnew;
            int qrow = mq + 8 * h2;
            float ps = 0.f;
            #pragma unroll
            for (int nf = 0; nf < 8; nf++) {
                float p0 = __expf(s[nf][base]     - mnew);
                float p1 = __expf(s[nf][base + 1] - mnew);
                ps += p0 + p1;
                int key = nf * 8 + 2 * c4;
                Ps[qrow * 68 + key]     = f2tf(p0);
                Ps[qrow * 68 + key + 1] = f2tf(p1);
            }
            ps += __shfl_xor_sync(0xffffffffu, ps, 1);
            ps += __shfl_xor_sync(0xffffffffu, ps, 2);
            lrow[h2] = lrow[h2] * corr + ps;
            #pragma unroll
            for (int nf = 0; nf < 16; nf++) {
                o[nf][base]     *= corr;
                o[nf][base + 1] *= corr;
            }
        }
        __syncwarp();

        if (ic + 1 < NIT) cp_wait<1>(); else cp_wait<0>();   // V(ic) ready
        __syncthreads();

        #pragma unroll
        for (int ks = 0; ks < 8; ks++) {
            int kk = ks * 8 + c4;
            uint32_t a[4];
            a[0] = Ps[mq * 68 + kk];
            a[1] = Ps[(mq + 8) * 68 + kk];
            a[2] = Ps[mq * 68 + kk + 4];
            a[3] = Ps[(mq + 8) * 68 + kk + 4];
            #pragma unroll
            for (int nf = 0; nf < 16; nf++) {
                int n = nf * 8 + r4;
                uint32_t bb[2];
                bb[0] = Vs[kk * 136 + n];
                bb[1] = Vs[(kk + 4) * 136 + n];
                mma_tf32(o[nf], a, bb);
            }
        }
        __syncthreads();   // all warps done reading Vs

        if (ic + 1 < NIT) {                              // prefetch V(ic+1)
            size_t gk = gk0 + (size_t)(ic + 1) * 64 * DMODEL;
            #pragma unroll
            for (int i = 0; i < 8; i++) {
                int row = srow + 8 * i;
                cpa16(s2u(&Vs[row * 136 + scol]), &V[gk + (size_t)row * DMODEL + scol]);
            }
            CP_COMMIT();
        }
    }

    float inv0 = 1.0f / lrow[0], inv1 = 1.0f / lrow[1];
    #pragma unroll
    for (int nf = 0; nf < 16; nf++) {
        int col = nf * 8 + 2 * c4;
        size_t base0 = gq + (size_t)mq * DMODEL + col;
        float2 o0 = make_float2(roundtf(o[nf][0] * inv0), roundtf(o[nf][1] * inv0));
        float2 o1 = make_float2(roundtf(o[nf][2] * inv1), roundtf(o[nf][3] * inv1));
        *(float2*)&O[base0]              = o0;
        *(float2*)&O[base0 + 8 * DMODEL] = o1;
    }
}

// -------- driver -------------------------------------------------------------
extern "C" void kernel_launch(void* const* d_in, const int* in_sizes, int n_in,
                              void* d_out, int out_size) {
    const float* x1    = (const float*)d_in[0];
    const float* x2    = (const float*)d_in[1];
    const float* ln1_g = (const float*)d_in[2];
    const float* ln1_b = (const float*)d_in[3];
    const float* ln2_g = (const float*)d_in[4];
    const float* ln2_b = (const float*)d_in[5];
    const float* lnf_g = (const float*)d_in[6];
    const float* lnf_b = (const float*)d_in[7];
    const float* Wq1  = (const float*)d_in[8];   const float* bq1  = (const float*)d_in[9];
    const float* Wk1  = (const float*)d_in[10];  const float* bk1  = (const float*)d_in[11];
    const float* Wv1  = (const float*)d_in[12];  const float* bv1  = (const float*)d_in[13];
    const float* Wq2  = (const float*)d_in[14];  const float* bq2  = (const float*)d_in[15];
    const float* Wk2  = (const float*)d_in[16];  const float* bk2  = (const float*)d_in[17];
    const float* Wv2  = (const float*)d_in[18];  const float* bv2  = (const float*)d_in[19];
    const float* Wq12 = (const float*)d_in[20];  const float* bq12 = (const float*)d_in[21];
    const float* Wk12 = (const float*)d_in[22];  const float* bk12 = (const float*)d_in[23];
    const float* Wv12 = (const float*)d_in[24];  const float* bv12 = (const float*)d_in[25];
    const float* Wo   = (const float*)d_in[26];  const float* bo   = (const float*)d_in[27];
    const float* W1   = (const float*)d_in[28];  const float* b1   = (const float*)d_in[29];
    const float* W2   = (const float*)d_in[30];  const float* b2   = (const float*)d_in[31];
    float* out = (float*)d_out;

    float *x1n, *x2n, *q, *k, *v, *ctx, *src1, *src2, *xres, *hbuf, *wr;
    cudaGetSymbolAddress((void**)&x1n,  g_x1n);
    cudaGetSymbolAddress((void**)&x2n,  g_x2n);
    cudaGetSymbolAddress((void**)&q,    g_q);
    cudaGetSymbolAddress((void**)&k,    g_k);
    cudaGetSymbolAddress((void**)&v,    g_v);
    cudaGetSymbolAddress((void**)&ctx,  g_ctx);
    cudaGetSymbolAddress((void**)&src1, g_src1);
    cudaGetSymbolAddress((void**)&src2, g_src2);
    cudaGetSymbolAddress((void**)&xres, g_xres);
    cudaGetSymbolAddress((void**)&hbuf, g_h);
    cudaGetSymbolAddress((void**)&wr,   g_wr);

    const float* Wq1r  = wr;
    const float* Wk1r  = wr + 1 * 262144;
    const float* Wv1r  = wr + 2 * 262144;
    const float* Wq2r  = wr + 3 * 262144;
    const float* Wk2r  = wr + 4 * 262144;
    const float* Wv2r  = wr + 5 * 262144;
    const float* Wq12r = wr + 6 * 262144;
    const float* Wk12r = wr + 7 * 262144;
    const float* Wv12r = wr + 8 * 262144;
    const float* Wor   = wr + 9 * 262144;
    const float* W1r   = wr + 2621440;
    const float* W2r   = wr + 3145728;

    cudaFuncSetAttribute(gemm_tc, cudaFuncAttributeMaxDynamicSharedMemorySize, GEMM_SMEM);
    cudaFuncSetAttribute(attn_tc, cudaFuncAttributeMaxDynamicSharedMemorySize, ATT_SMEM);

    dim3 gAttn(SEQ / 128, NHEAD, BATCH);
    dim3 g512 (DMODEL / 128, MROWS / 128);
    dim3 g1024(DMLP   / 128, MROWS / 128);
    const float qs = 0.08838834764831845f;   // 1/sqrt(128)
    const int RD = FLAG_ROUND;

    WPtrs wp;
    wp.s[0] = Wq1;  wp.s[1] = Wk1;  wp.s[2] = Wv1;
    wp.s[3] = Wq2;  wp.s[4] = Wk2;  wp.s[5] = Wv2;
    wp.s[6] = Wq12; wp.s[7] = Wk12; wp.s[8] = Wv12;
    wp.s[9] = Wo;   wp.s[10] = W1;  wp.s[11] = W2;
    round_w<<<3584, 256>>>(wp, wr);

    ln_kernel<<<MROWS, 128>>>(x1, ln1_g, ln1_b, x1n);
    ln_kernel<<<MROWS, 128>>>(x2, ln2_g, ln2_b, x2n);

    // stream-1 self-attention (Q projection pre-scaled by 1/sqrt(hd))
    gemm_tc<<<g512, 256, GEMM_SMEM>>>(x1n, Wq1r, bq1, nullptr, q, MROWS, DMODEL, DMODEL, RD, qs);
    gemm_tc<<<g512, 256, GEMM_SMEM>>>(x1n, Wk1r, bk1, nullptr, k, MROWS, DMODEL, DMODEL, RD, 1.f);
    gemm_tc<<<g512, 256, GEMM_SMEM>>>(x1n, Wv1r, bv1, nullptr, v, MROWS, DMODEL, DMODEL, RD, 1.f);
    attn_tc<<<gAttn, 256, ATT_SMEM>>>(q, k, v, ctx);
    gemm_tc<<<g512, 256, GEMM_SMEM>>>(ctx, Wor, bo, x1n, src1, MROWS, DMODEL, DMODEL, RD, 1.f);

    // stream-2 self-attention
    gemm_tc<<<g512, 256, GEMM_SMEM>>>(x2n, Wq2r, bq2, nullptr, q, MROWS, DMODEL, DMODEL, RD, qs);
    gemm_tc<<<g512, 256, GEMM_SMEM>>>(x2n, Wk2r, bk2, nullptr, k, MROWS, DMODEL, DMODEL, RD, 1.f);
    gemm_tc<<<g512, 256, GEMM_SMEM>>>(x2n, Wv2r, bv2, nullptr, v, MROWS, DMODEL, DMODEL, RD, 1.f);
    attn_tc<<<gAttn, 256, ATT_SMEM>>>(q, k, v, ctx);
    gemm_tc<<<g512, 256, GEMM_SMEM>>>(ctx, Wor, bo, x2n, src2, MROWS, DMODEL, DMODEL, RD, 1.f);

    // cross attention: Q from src1, K/V from src2
    gemm_tc<<<g512, 256, GEMM_SMEM>>>(src1, Wq12r, bq12, nullptr, q, MROWS, DMODEL, DMODEL, RD, qs);
    gemm_tc<<<g512, 256, GEMM_SMEM>>>(src2, Wk12r, bk12, nullptr, k, MROWS, DMODEL, DMODEL, RD, 1.f);
    gemm_tc<<<g512, 256, GEMM_SMEM>>>(src2, Wv12r, bv12, nullptr, v, MROWS, DMODEL, DMODEL, RD, 1.f);
    attn_tc<<<gAttn, 256, ATT_SMEM>>>(q, k, v, ctx);
    gemm_tc<<<g512, 256, GEMM_SMEM>>>(ctx, Wor, bo, x1, xres, MROWS, DMODEL, DMODEL, 0, 1.f);

    // final LN + MLP
    ln_kernel<<<MROWS, 128>>>(xres, lnf_g, lnf_b, x1n);
    gemm_tc<<<g1024, 256, GEMM_SMEM>>>(x1n, W1r, b1, nullptr, hbuf, MROWS, DMLP, DMODEL,
                                       FLAG_GELU | FLAG_ROUND, 1.f);
    gemm_tc<<<g512, 256, GEMM_SMEM>>>(hbuf, W2r, b2, xres, out, MROWS, DMODEL, DMLP, 0, 1.f);
}

// round 5
// speedup vs baseline: 1.8684x; 1.5956x over previous
#include <cuda_runtime.h>
#include <cuda_bf16.h>
#include <math.h>
#include <stdint.h>

#define BATCH 16
#define SEQ   1024
#define DMODEL 512
#define NHEAD 4
#define HDIM  128
#define MROWS (BATCH * SEQ)
#define DMLP  1024

typedef __nv_bfloat16 bf16;

__device__ bf16  g_x1n [MROWS * DMODEL];
__device__ bf16  g_x2n [MROWS * DMODEL];
__device__ bf16  g_q   [MROWS * DMODEL];
__device__ bf16  g_k   [MROWS * DMODEL];
__device__ bf16  g_v   [MROWS * DMODEL];
__device__ bf16  g_ctx [MROWS * DMODEL];
__device__ bf16  g_src1[MROWS * DMODEL];
__device__ bf16  g_src2[MROWS * DMODEL];
__device__ float g_xres[MROWS * DMODEL];
__device__ bf16  g_h   [MROWS * DMLP];
__device__ bf16  g_wr  [10 * DMODEL * DMODEL + 2 * DMODEL * DMLP];

__device__ __forceinline__ uint32_t s2u(const void* p) {
    return (uint32_t)__cvta_generic_to_shared(p);
}
__device__ __forceinline__ void cpa16(uint32_t dst, const void* src) {
    asm volatile("cp.async.cg.shared.global [%0], [%1], 16;" :: "r"(dst), "l"(src));
}
#define CP_COMMIT() asm volatile("cp.async.commit_group;")
template <int N> __device__ __forceinline__ void cp_wait() {
    asm volatile("cp.async.wait_group %0;" :: "n"(N));
}
__device__ __forceinline__ void ldsm4(uint32_t* r, uint32_t a) {
    asm volatile("ldmatrix.sync.aligned.m8n8.x4.shared.b16 {%0,%1,%2,%3}, [%4];"
                 : "=r"(r[0]), "=r"(r[1]), "=r"(r[2]), "=r"(r[3]) : "r"(a));
}
__device__ __forceinline__ void ldsm4t(uint32_t* r, uint32_t a) {
    asm volatile("ldmatrix.sync.aligned.m8n8.x4.trans.shared.b16 {%0,%1,%2,%3}, [%4];"
                 : "=r"(r[0]), "=r"(r[1]), "=r"(r[2]), "=r"(r[3]) : "r"(a));
}
__device__ __forceinline__ void mma_bf(float* c, const uint32_t* a, const uint32_t* b) {
    asm volatile(
        "mma.sync.aligned.m16n8k16.row.col.f32.bf16.bf16.f32 "
        "{%0,%1,%2,%3}, {%4,%5,%6,%7}, {%8,%9}, {%0,%1,%2,%3};"
        : "+f"(c[0]), "+f"(c[1]), "+f"(c[2]), "+f"(c[3])
        : "r"(a[0]), "r"(a[1]), "r"(a[2]), "r"(a[3]), "r"(b[0]), "r"(b[1]));
}
__device__ __forceinline__ uint32_t packbf(float x, float y) {
    __nv_bfloat162 h = __floats2bfloat162_rn(x, y);
    return *(uint32_t*)&h;
}

// -------- weight convert to bf16 --------------------------------------------
struct WPtrs { const float* s[12]; };
__global__ void round_w(WPtrs p, bf16* dst) {
    int t = blockIdx.x * blockDim.x + threadIdx.x;
    int idx = t * 8;
    if (idx >= 3670016) return;
    int a, off;
    if (idx < 2621440) { a = idx >> 18; off = idx & 262143; }
    else { int r = idx - 2621440; a = 10 + (r >> 19); off = r & 524287; }
    float4 v0 = *(const float4*)&p.s[a][off];
    float4 v1 = *(const float4*)&p.s[a][off + 4];
    uint32_t h[4] = { packbf(v0.x, v0.y), packbf(v0.z, v0.w),
                      packbf(v1.x, v1.y), packbf(v1.z, v1.w) };
    *(uint4*)&dst[idx] = *(uint4*)h;
}

// -------- LayerNorm: fp32 in, bf16 out --------------------------------------
__global__ void ln_kernel(const float* __restrict__ x, const float* __restrict__ g,
                          const float* __restrict__ b, bf16* __restrict__ y) {
    int row = blockIdx.x, t = threadIdx.x;
    const float* xr = x + (size_t)row * DMODEL;
    float4 v4 = ((const float4*)xr)[t];
    __shared__ float red[4];
    float s = v4.x + v4.y + v4.z + v4.w;
    #pragma unroll
    for (int o = 16; o; o >>= 1) s += __shfl_xor_sync(0xffffffffu, s, o);
    if ((t & 31) == 0) red[t >> 5] = s;
    __syncthreads();
    float mean = (red[0] + red[1] + red[2] + red[3]) * (1.0f / DMODEL);
    __syncthreads();
    float dx = v4.x - mean, dy = v4.y - mean, dz = v4.z - mean, dw = v4.w - mean;
    float vs = dx*dx + dy*dy + dz*dz + dw*dw;
    #pragma unroll
    for (int o = 16; o; o >>= 1) vs += __shfl_xor_sync(0xffffffffu, vs, o);
    if ((t & 31) == 0) red[t >> 5] = vs;
    __syncthreads();
    float var = (red[0] + red[1] + red[2] + red[3]) * (1.0f / DMODEL);
    float inv = rsqrtf(var + 1e-6f);
    float4 g4 = ((const float4*)g)[t];
    float4 b4 = ((const float4*)b)[t];
    uint32_t h[2] = { packbf(dx * inv * g4.x + b4.x, dy * inv * g4.y + b4.y),
                      packbf(dz * inv * g4.z + b4.z, dw * inv * g4.w + b4.w) };
    *(uint2*)&y[(size_t)row * DMODEL + t * 4] = *(uint2*)h;
}

// -------- bf16 GEMM, cp.async + ldmatrix ------------------------------------
// tile 128x128, BK=32, 8 warps (wm64 x wn32). A [m][k] pitch 40, B [k][n] pitch 136.
#define GAB (128 * 80)           // A buffer bytes
#define GBB (32 * 272)           // B buffer bytes
#define GEMM_SMEM (2 * (GAB + GBB))

template<int OUTF32>
__global__ __launch_bounds__(256, 2)
void gemm_bf(const bf16* __restrict__ A, const bf16* __restrict__ W,
             const float* __restrict__ bias,
             const bf16* __restrict__ residh, const float* __restrict__ residf,
             float* __restrict__ Cf, bf16* __restrict__ Ch,
             int M, int N, int K, int gelu, float oscale) {
    extern __shared__ char smraw[];
    uint32_t smA = s2u(smraw);            // [2][128][40] bf16
    uint32_t smB = smA + 2 * GAB;         // [2][32][136] bf16

    int tid = threadIdx.x, lane = tid & 31, wid = tid >> 5;
    int m0 = blockIdx.y * 128, n0 = blockIdx.x * 128;
    int wm = (wid & 1) * 64, wn = (wid >> 1) * 32;

    float acc[4][4][4];
    #pragma unroll
    for (int i = 0; i < 4; i++)
        #pragma unroll
        for (int j = 0; j < 4; j++)
            #pragma unroll
            for (int k = 0; k < 4; k++) acc[i][j][k] = 0.f;

    int ar = tid >> 1, ag = (tid & 1) * 2;
    int br = tid >> 4, bg = tid & 15;

    auto stage = [&](int buf, int k0) {
        uint32_t da = smA + buf * GAB + ar * 80 + ag * 16;
        const bf16* sa = A + (size_t)(m0 + ar) * K + k0 + ag * 8;
        cpa16(da, sa); cpa16(da + 16, sa + 8);
        #pragma unroll
        for (int i = 0; i < 2; i++) {
            int r = br + 16 * i;
            cpa16(smB + buf * GBB + r * 272 + bg * 16,
                  W + (size_t)(k0 + r) * N + n0 + bg * 8);
        }
        CP_COMMIT();
    };

    stage(0, 0);
    int T = K >> 5;
    // fragment lane offsets
    int l15 = lane & 15, lh8 = (lane >> 4) << 3;

    for (int it = 0; it < T; it++) {
        cp_wait<0>();
        __syncthreads();
        if (it + 1 < T) stage((it + 1) & 1, (it + 1) * 32);
        uint32_t Ab = smA + (it & 1) * GAB;
        uint32_t Bb = smB + (it & 1) * GBB;
        #pragma unroll
        for (int kk = 0; kk < 32; kk += 16) {
            uint32_t a[4][4];
            #pragma unroll
            for (int mf = 0; mf < 4; mf++)
                ldsm4(a[mf], Ab + ((wm + mf * 16 + l15) * 40 + kk + lh8) * 2);
            #pragma unroll
            for (int nb = 0; nb < 2; nb++) {
                uint32_t b[4];
                ldsm4t(b, Bb + ((kk + l15) * 136 + wn + nb * 16 + lh8) * 2);
                #pragma unroll
                for (int mf = 0; mf < 4; mf++) {
                    mma_bf(acc[mf][nb * 2 + 0], a[mf], b + 0);
                    mma_bf(acc[mf][nb * 2 + 1], a[mf], b + 2);
                }
            }
        }
        __syncthreads();
    }

    int r4 = lane >> 2, c2 = (lane & 3) * 2;
    #pragma unroll
    for (int mf = 0; mf < 4; mf++) {
        #pragma unroll
        for (int nf = 0; nf < 4; nf++) {
            int row = m0 + wm + mf * 16 + r4;
            int col = n0 + wn + nf * 8 + c2;
            float2 bi = *(const float2*)&bias[col];
            #pragma unroll
            for (int hh = 0; hh < 2; hh++) {
                int r = row + hh * 8;
                float v0 = acc[mf][nf][hh * 2 + 0] + bi.x;
                float v1 = acc[mf][nf][hh * 2 + 1] + bi.y;
                if (residh) {
                    uint32_t rp = *(const uint32_t*)&residh[(size_t)r * N + col];
                    float2 rr = __bfloat1622float2(*(__nv_bfloat162*)&rp);
                    v0 += rr.x; v1 += rr.y;
                }
                if (residf) {
                    float2 rr = *(const float2*)&residf[(size_t)r * N + col];
                    v0 += rr.x; v1 += rr.y;
                }
                if (gelu) {
                    v0 = 0.5f * v0 * (1.0f + erff(v0 * 0.70710678118654752f));
                    v1 = 0.5f * v1 * (1.0f + erff(v1 * 0.70710678118654752f));
                }
                v0 *= oscale; v1 *= oscale;
                if (OUTF32) *(float2*)&Cf[(size_t)r * N + col] = make_float2(v0, v1);
                else *(uint32_t*)&Ch[(size_t)r * N + col] = packbf(v0, v1);
            }
        }
    }
}

// -------- bf16 flash attention ----------------------------------------------
// grid (SEQ/128, NHEAD, BATCH), 8 warps x 16 q-rows. 64-key chunks.
// Qs[128][136], Ks[2][64][136], Vs[64][136], Ps[128][72] (bf16).
#define AQB (128 * 272)
#define AKB (64 * 272)
#define AVB (64 * 272)
#define APB (128 * 144)
#define ATT_SMEM (AQB + 2 * AKB + AVB + APB)
#define NIT (SEQ / 64)

__global__ __launch_bounds__(256, 1)
void attn_bf(const bf16* __restrict__ Q, const bf16* __restrict__ K,
             const bf16* __restrict__ V, bf16* __restrict__ O) {
    extern __shared__ char smraw[];
    uint32_t smQ = s2u(smraw);
    uint32_t smK = smQ + AQB;
    uint32_t smV = smK + 2 * AKB;
    uint32_t smP = smV + AVB;
    bf16* Pp = (bf16*)(smraw + AQB + 2 * AKB + AVB);

    int tid = threadIdx.x, lane = tid & 31, wid = tid >> 5;
    int q0 = blockIdx.x * 128, h = blockIdx.y, b = blockIdx.z;
    size_t gq  = ((size_t)b * SEQ + q0) * DMODEL + (size_t)h * HDIM;
    size_t gk0 = ((size_t)b * SEQ) * DMODEL + (size_t)h * HDIM;
    int sr = tid >> 4, sg = tid & 15;

    #pragma unroll
    for (int i = 0; i < 8; i++) {
        int r = sr + 16 * i;
        cpa16(smQ + r * 272 + sg * 16, Q + gq + (size_t)r * DMODEL + sg * 8);
    }
    CP_COMMIT();
    #pragma unroll
    for (int i = 0; i < 4; i++) {
        int r = sr + 16 * i;
        cpa16(smK + r * 272 + sg * 16, K + gk0 + (size_t)r * DMODEL + sg * 8);
    }
    CP_COMMIT();
    #pragma unroll
    for (int i = 0; i < 4; i++) {
        int r = sr + 16 * i;
        cpa16(smV + r * 272 + sg * 16, V + gk0 + (size_t)r * DMODEL + sg * 8);
    }
    CP_COMMIT();
    cp_wait<0>();
    __syncthreads();

    float mrow[2] = {-1e30f, -1e30f}, lrow[2] = {0.f, 0.f};
    float o[16][4];
    #pragma unroll
    for (int i = 0; i < 16; i++)
        #pragma unroll
        for (int j = 0; j < 4; j++) o[i][j] = 0.f;

    int r4 = lane >> 2, c4 = lane & 3;
    int l15 = lane & 15, lh8 = (lane >> 4) << 3;
    int mq = wid * 16 + r4;

    for (int ic = 0; ic < NIT; ic++) {
        if (ic > 0) { cp_wait<1>(); __syncthreads(); }
        uint32_t Kb = smK + (ic & 1) * AKB;

        if (ic + 1 < NIT) {
            size_t gk = gk0 + (size_t)(ic + 1) * 64 * DMODEL;
            #pragma unroll
            for (int i = 0; i < 4; i++) {
                int r = sr + 16 * i;
                cpa16(smK + ((ic + 1) & 1) * AKB + r * 272 + sg * 16,
                      K + gk + (size_t)r * DMODEL + sg * 8);
            }
            CP_COMMIT();
        }

        // S = Q @ K^T  (16 x 64 per warp)
        float s[8][4];
        #pragma unroll
        for (int nf = 0; nf < 8; nf++)
            #pragma unroll
            for (int j = 0; j < 4; j++) s[nf][j] = 0.f;

        #pragma unroll
        for (int kd = 0; kd < 8; kd++) {
            uint32_t qa[4];
            ldsm4(qa, smQ + ((wid * 16 + l15) * 136 + kd * 16 + lh8) * 2);
            #pragma unroll
            for (int kb = 0; kb < 4; kb++) {
                uint32_t kf[4];
                ldsm4(kf, Kb + ((kb * 16 + (lane & 7) + lh8) * 136
                                + kd * 16 + (lane & 8)) * 2);
                mma_bf(s[kb * 2 + 0], qa, kf + 0);
                mma_bf(s[kb * 2 + 1], qa, kf + 2);
            }
        }

        // online softmax per row-half
        #pragma unroll
        for (int h2 = 0; h2 < 2; h2++) {
            int base = h2 * 2;
            float mx = -1e30f;
            #pragma unroll
            for (int nf = 0; nf < 8; nf++)
                mx = fmaxf(mx, fmaxf(s[nf][base], s[nf][base + 1]));
            mx = fmaxf(mx, __shfl_xor_sync(0xffffffffu, mx, 1));
            mx = fmaxf(mx, __shfl_xor_sync(0xffffffffu, mx, 2));
            float mnew = fmaxf(mrow[h2], mx);
            float corr = __expf(mrow[h2] - mnew);
            mrow[h2] = mnew;
            int qrow = mq + 8 * h2;
            float ps = 0.f;
            #pragma unroll
            for (int nf = 0; nf < 8; nf++) {
                float p0 = __expf(s[nf][base]     - mnew);
                float p1 = __expf(s[nf][base + 1] - mnew);
                ps += p0 + p1;
                *(uint32_t*)&Pp[qrow * 72 + nf * 8 + 2 * c4] = packbf(p0, p1);
            }
            ps += __shfl_xor_sync(0xffffffffu, ps, 1);
            ps += __shfl_xor_sync(0xffffffffu, ps, 2);
            lrow[h2] = lrow[h2] * corr + ps;
            #pragma unroll
            for (int nf = 0; nf < 16; nf++) {
                o[nf][base]     *= corr;
                o[nf][base + 1] *= corr;
            }
        }
        __syncwarp();

        if (ic + 1 < NIT) cp_wait<1>(); else cp_wait<0>();
        __syncthreads();

        // O += P @ V  (16 x 128 per warp)
        #pragma unroll
        for (int kc = 0; kc < 4; kc++) {
            uint32_t pa[4];
            ldsm4(pa, smP + ((wid * 16 + l15) * 72 + kc * 16 + lh8) * 2);
            #pragma unroll
            for (int nb = 0; nb < 8; nb++) {
                uint32_t vb[4];
                ldsm4t(vb, smV + ((kc * 16 + l15) * 136 + nb * 16 + lh8) * 2);
                mma_bf(o[nb * 2 + 0], pa, vb + 0);
                mma_bf(o[nb * 2 + 1], pa, vb + 2);
            }
        }
        __syncthreads();

        if (ic + 1 < NIT) {
            size_t gk = gk0 + (size_t)(ic + 1) * 64 * DMODEL;
            #pragma unroll
            for (int i = 0; i < 4; i++) {
                int r = sr + 16 * i;
                cpa16(smV + r * 272 + sg * 16, V + gk + (size_t)r * DMODEL + sg * 8);
            }
            CP_COMMIT();
        }
    }

    float inv0 = 1.0f / lrow[0], inv1 = 1.0f / lrow[1];
    #pragma unroll
    for (int nf = 0; nf < 16; nf++) {
        int col = nf * 8 + 2 * c4;
        size_t base0 = gq + (size_t)mq * DMODEL + col;
        *(uint32_t*)&O[base0]              = packbf(o[nf][0] * inv0, o[nf][1] * inv0);
        *(uint32_t*)&O[base0 + 8 * DMODEL] = packbf(o[nf][2] * inv1, o[nf][3] * inv1);
    }
}

// -------- driver -------------------------------------------------------------
extern "C" void kernel_launch(void* const* d_in, const int* in_sizes, int n_in,
                              void* d_out, int out_size) {
    const float* x1    = (const float*)d_in[0];
    const float* x2    = (const float*)d_in[1];
    const float* ln1_g = (const float*)d_in[2];
    const float* ln1_b = (const float*)d_in[3];
    const float* ln2_g = (const float*)d_in[4];
    const float* ln2_b = (const float*)d_in[5];
    const float* lnf_g = (const float*)d_in[6];
    const float* lnf_b = (const float*)d_in[7];
    const float* bq1  = (const float*)d_in[9];
    const float* bk1  = (const float*)d_in[11];
    const float* bv1  = (const float*)d_in[13];
    const float* bq2  = (const float*)d_in[15];
    const float* bk2  = (const float*)d_in[17];
    const float* bv2  = (const float*)d_in[19];
    const float* bq12 = (const float*)d_in[21];
    const float* bk12 = (const float*)d_in[23];
    const float* bv12 = (const float*)d_in[25];
    const float* bo   = (const float*)d_in[27];
    const float* b1   = (const float*)d_in[29];
    const float* b2   = (const float*)d_in[31];
    float* out = (float*)d_out;

    bf16 *x1n, *x2n, *q, *k, *v, *ctx, *src1, *src2, *hbuf, *wr;
    float* xres;
    cudaGetSymbolAddress((void**)&x1n,  g_x1n);
    cudaGetSymbolAddress((void**)&x2n,  g_x2n);
    cudaGetSymbolAddress((void**)&q,    g_q);
    cudaGetSymbolAddress((void**)&k,    g_k);
    cudaGetSymbolAddress((void**)&v,    g_v);
    cudaGetSymbolAddress((void**)&ctx,  g_ctx);
    cudaGetSymbolAddress((void**)&src1, g_src1);
    cudaGetSymbolAddress((void**)&src2, g_src2);
    cudaGetSymbolAddress((void**)&xres, g_xres);
    cudaGetSymbolAddress((void**)&hbuf, g_h);
    cudaGetSymbolAddress((void**)&wr,   g_wr);

    const bf16* Wq1r  = wr;
    const bf16* Wk1r  = wr + 1 * 262144;
    const bf16* Wv1r  = wr + 2 * 262144;
    const bf16* Wq2r  = wr + 3 * 262144;
    const bf16* Wk2r  = wr + 4 * 262144;
    const bf16* Wv2r  = wr + 5 * 262144;
    const bf16* Wq12r = wr + 6 * 262144;
    const bf16* Wk12r = wr + 7 * 262144;
    const bf16* Wv12r = wr + 8 * 262144;
    const bf16* Wor   = wr + 9 * 262144;
    const bf16* W1r   = wr + 2621440;
    const bf16* W2r   = wr + 3145728;

    cudaFuncSetAttribute(gemm_bf<0>, cudaFuncAttributeMaxDynamicSharedMemorySize, GEMM_SMEM);
    cudaFuncSetAttribute(gemm_bf<1>, cudaFuncAttributeMaxDynamicSharedMemorySize, GEMM_SMEM);
    cudaFuncSetAttribute(attn_bf, cudaFuncAttributeMaxDynamicSharedMemorySize, ATT_SMEM);

    dim3 gAttn(SEQ / 128, NHEAD, BATCH);
    dim3 g512 (DMODEL / 128, MROWS / 128);
    dim3 g1024(DMLP   / 128, MROWS / 128);
    const float qs = 0.08838834764831845f;

    WPtrs wp;
    wp.s[0] = (const float*)d_in[8];  wp.s[1] = (const float*)d_in[10];
    wp.s[2] = (const float*)d_in[12]; wp.s[3] = (const float*)d_in[14];
    wp.s[4] = (const float*)d_in[16]; wp.s[5] = (const float*)d_in[18];
    wp.s[6] = (const float*)d_in[20]; wp.s[7] = (const float*)d_in[22];
    wp.s[8] = (const float*)d_in[24]; wp.s[9] = (const float*)d_in[26];
    wp.s[10] = (const float*)d_in[28]; wp.s[11] = (const float*)d_in[30];
    round_w<<<1792, 256>>>(wp, wr);

    ln_kernel<<<MROWS, 128>>>(x1, ln1_g, ln1_b, x1n);
    ln_kernel<<<MROWS, 128>>>(x2, ln2_g, ln2_b, x2n);

    // stream-1 self-attention (Q projection scaled by 1/sqrt(hd))
    gemm_bf<0><<<g512, 256, GEMM_SMEM>>>(x1n, Wq1r, bq1, nullptr, nullptr, nullptr, q, MROWS, DMODEL, DMODEL, 0, qs);
    gemm_bf<0><<<g512, 256, GEMM_SMEM>>>(x1n, Wk1r, bk1, nullptr, nullptr, nullptr, k, MROWS, DMODEL, DMODEL, 0, 1.f);
    gemm_bf<0><<<g512, 256, GEMM_SMEM>>>(x1n, Wv1r, bv1, nullptr, nullptr, nullptr, v, MROWS, DMODEL, DMODEL, 0, 1.f);
    attn_bf<<<gAttn, 256, ATT_SMEM>>>(q, k, v, ctx);
    gemm_bf<0><<<g512, 256, GEMM_SMEM>>>(ctx, Wor, bo, x1n, nullptr, nullptr, src1, MROWS, DMODEL, DMODEL, 0, 1.f);

    // stream-2 self-attention
    gemm_bf<0><<<g512, 256, GEMM_SMEM>>>(x2n, Wq2r, bq2, nullptr, nullptr, nullptr, q, MROWS, DMODEL, DMODEL, 0, qs);
    gemm_bf<0><<<g512, 256, GEMM_SMEM>>>(x2n, Wk2r, bk2, nullptr, nullptr, nullptr, k, MROWS, DMODEL, DMODEL, 0, 1.f);
    gemm_bf<0><<<g512, 256, GEMM_SMEM>>>(x2n, Wv2r, bv2, nullptr, nullptr, nullptr, v, MROWS, DMODEL, DMODEL, 0, 1.f);
    attn_bf<<<gAttn, 256, ATT_SMEM>>>(q, k, v, ctx);
    gemm_bf<0><<<g512, 256, GEMM_SMEM>>>(ctx, Wor, bo, x2n, nullptr, nullptr, src2, MROWS, DMODEL, DMODEL, 0, 1.f);

    // cross attention: Q from src1, K/V from src2; residual = original x1 (fp32)
    gemm_bf<0><<<g512, 256, GEMM_SMEM>>>(src1, Wq12r, bq12, nullptr, nullptr, nullptr, q, MROWS, DMODEL, DMODEL, 0, qs);
    gemm_bf<0><<<g512, 256, GEMM_SMEM>>>(src2, Wk12r, bk12, nullptr, nullptr, nullptr, k, MROWS, DMODEL, DMODEL, 0, 1.f);
    gemm_bf<0><<<g512, 256, GEMM_SMEM>>>(src2, Wv12r, bv12, nullptr, nullptr, nullptr, v, MROWS, DMODEL, DMODEL, 0, 1.f);
    attn_bf<<<gAttn, 256, ATT_SMEM>>>(q, k, v, ctx);
    gemm_bf<1><<<g512, 256, GEMM_SMEM>>>(ctx, Wor, bo, nullptr, x1, xres, nullptr, MROWS, DMODEL, DMODEL, 0, 1.f);

    // final LN + MLP; out = xres + gelu(h@W1+b1)@W2+b2
    ln_kernel<<<MROWS, 128>>>(xres, lnf_g, lnf_b, x1n);
    gemm_bf<0><<<g1024, 256, GEMM_SMEM>>>(x1n, W1r, b1, nullptr, nullptr, nullptr, hbuf, MROWS, DMLP, DMODEL, 1, 1.f);
    gemm_bf<1><<<g512, 256, GEMM_SMEM>>>(hbuf, W2r, b2, nullptr, xres, out, nullptr, MROWS, DMODEL, DMLP, 0, 1.f);
}

// round 6
// speedup vs baseline: 1.9027x; 1.0183x over previous
#include <cuda_runtime.h>
#include <cuda_bf16.h>
#include <math.h>
#include <stdint.h>

#define BATCH 16
#define SEQ   1024
#define DMODEL 512
#define NHEAD 4
#define HDIM  128
#define MROWS (BATCH * SEQ)
#define DMLP  1024

typedef __nv_bfloat16 bf16;

__device__ bf16  g_x1n [MROWS * DMODEL];
__device__ bf16  g_x2n [MROWS * DMODEL];
__device__ bf16  g_q   [MROWS * DMODEL];
__device__ bf16  g_k   [MROWS * DMODEL];
__device__ bf16  g_v   [MROWS * DMODEL];
__device__ bf16  g_ctx [MROWS * DMODEL];
__device__ bf16  g_src1[MROWS * DMODEL];
__device__ bf16  g_src2[MROWS * DMODEL];
__device__ float g_xres[MROWS * DMODEL];
__device__ bf16  g_h   [MROWS * DMLP];
__device__ bf16  g_wr  [3670016];
__device__ float g_bqkv[4608];

__device__ __forceinline__ uint32_t s2u(const void* p) {
    return (uint32_t)__cvta_generic_to_shared(p);
}
__device__ __forceinline__ void cpa16(uint32_t dst, const void* src) {
    asm volatile("cp.async.cg.shared.global [%0], [%1], 16;" :: "r"(dst), "l"(src));
}
#define CP_COMMIT() asm volatile("cp.async.commit_group;")
template <int N> __device__ __forceinline__ void cp_wait() {
    asm volatile("cp.async.wait_group %0;" :: "n"(N));
}
__device__ __forceinline__ void ldsm4(uint32_t* r, uint32_t a) {
    asm volatile("ldmatrix.sync.aligned.m8n8.x4.shared.b16 {%0,%1,%2,%3}, [%4];"
                 : "=r"(r[0]), "=r"(r[1]), "=r"(r[2]), "=r"(r[3]) : "r"(a));
}
__device__ __forceinline__ void ldsm4t(uint32_t* r, uint32_t a) {
    asm volatile("ldmatrix.sync.aligned.m8n8.x4.trans.shared.b16 {%0,%1,%2,%3}, [%4];"
                 : "=r"(r[0]), "=r"(r[1]), "=r"(r[2]), "=r"(r[3]) : "r"(a));
}
__device__ __forceinline__ void mma_bf(float* c, const uint32_t* a, const uint32_t* b) {
    asm volatile(
        "mma.sync.aligned.m16n8k16.row.col.f32.bf16.bf16.f32 "
        "{%0,%1,%2,%3}, {%4,%5,%6,%7}, {%8,%9}, {%0,%1,%2,%3};"
        : "+f"(c[0]), "+f"(c[1]), "+f"(c[2]), "+f"(c[3])
        : "r"(a[0]), "r"(a[1]), "r"(a[2]), "r"(a[3]), "r"(b[0]), "r"(b[1]));
}
__device__ __forceinline__ uint32_t packbf(float x, float y) {
    __nv_bfloat162 h = __floats2bfloat162_rn(x, y);
    return *(uint32_t*)&h;
}

// -------- weight repack: fused QKV [512][1536] x3 + Wo + W1 + W2 -------------
struct WPtrs { const float* s[12]; };
__global__ void round_w(WPtrs p, bf16* dst, float qs) {
    int t = blockIdx.x * blockDim.x + threadIdx.x;
    int idx = t * 8;
    if (idx >= 3670016) return;
    const float* src; float sc = 1.f; int off;
    if (idx < 2359296) {
        int s = idx / 786432, rem = idx % 786432;
        int kk = rem / 1536, n = rem % 1536;
        int m = n >> 9;
        src = p.s[s * 3 + m];
        off = kk * 512 + (n & 511);
        if (m == 0) sc = qs;
    } else if (idx < 2621440) { src = p.s[9];  off = idx - 2359296; }
    else if (idx < 3145728)   { src = p.s[10]; off = idx - 2621440; }
    else                      { src = p.s[11]; off = idx - 3145728; }
    float4 v0 = *(const float4*)&src[off];
    float4 v1 = *(const float4*)&src[off + 4];
    uint32_t h[4] = { packbf(v0.x*sc, v0.y*sc), packbf(v0.z*sc, v0.w*sc),
                      packbf(v1.x*sc, v1.y*sc), packbf(v1.z*sc, v1.w*sc) };
    *(uint4*)&dst[idx] = *(uint4*)h;
}

struct BPtrs { const float* s[9]; };
__global__ void round_b(BPtrs p, float* dst, float qs) {
    int i = blockIdx.x * blockDim.x + threadIdx.x;
    if (i >= 4608) return;
    int s = i / 1536, n = i % 1536, m = n >> 9;
    float v = p.s[s * 3 + m][n & 511];
    dst[i] = (m == 0) ? v * qs : v;
}

// -------- LayerNorm: fp32 in, bf16 out --------------------------------------
__global__ void ln_kernel(const float* __restrict__ x, const float* __restrict__ g,
                          const float* __restrict__ b, bf16* __restrict__ y) {
    int row = blockIdx.x, t = threadIdx.x;
    const float* xr = x + (size_t)row * DMODEL;
    float4 v4 = ((const float4*)xr)[t];
    __shared__ float red[4];
    float s = v4.x + v4.y + v4.z + v4.w;
    #pragma unroll
    for (int o = 16; o; o >>= 1) s += __shfl_xor_sync(0xffffffffu, s, o);
    if ((t & 31) == 0) red[t >> 5] = s;
    __syncthreads();
    float mean = (red[0] + red[1] + red[2] + red[3]) * (1.0f / DMODEL);
    __syncthreads();
    float dx = v4.x - mean, dy = v4.y - mean, dz = v4.z - mean, dw = v4.w - mean;
    float vs = dx*dx + dy*dy + dz*dz + dw*dw;
    #pragma unroll
    for (int o = 16; o; o >>= 1) vs += __shfl_xor_sync(0xffffffffu, vs, o);
    if ((t & 31) == 0) red[t >> 5] = vs;
    __syncthreads();
    float var = (red[0] + red[1] + red[2] + red[3]) * (1.0f / DMODEL);
    float inv = rsqrtf(var + 1e-6f);
    float4 g4 = ((const float4*)g)[t];
    float4 b4 = ((const float4*)b)[t];
    uint32_t h[2] = { packbf(dx * inv * g4.x + b4.x, dy * inv * g4.y + b4.y),
                      packbf(dz * inv * g4.z + b4.z, dw * inv * g4.w + b4.w) };
    *(uint2*)&y[(size_t)row * DMODEL + t * 4] = *(uint2*)h;
}

// -------- shared GEMM tile machinery (BK=64) ---------------------------------
#define GAB (128 * 144)          // A buffer bytes: [128][72] bf16
#define GBB (64 * 272)           // B buffer bytes: [64][136] bf16
#define GEMM_SMEM (2 * (GAB + GBB))

// stage one 128x64 A tile + 64x128 B tile
__device__ __forceinline__ void g_stage(uint32_t smA, uint32_t smB, int buf,
                                        const bf16* A, const bf16* W,
                                        int m0, int n0, int k0, int K, int N, int tid) {
    int ar = tid >> 1, ag = (tid & 1) * 4;
    uint32_t da = smA + buf * GAB + ar * 144 + ag * 16;
    const bf16* sa = A + (size_t)(m0 + ar) * K + k0 + ag * 8;
    #pragma unroll
    for (int i = 0; i < 4; i++) cpa16(da + i * 16, sa + i * 8);
    int br = tid >> 2, bg = (tid & 3) * 4;
    uint32_t db = smB + buf * GBB + br * 272 + bg * 16;
    const bf16* sb = W + (size_t)(k0 + br) * N + n0 + bg * 8;
    #pragma unroll
    for (int i = 0; i < 4; i++) cpa16(db + i * 16, sb + i * 8);
    CP_COMMIT();
}

// compute one BK=64 tile into acc[4][4][4]
__device__ __forceinline__ void g_tile(float acc[4][4][4], uint32_t Ab, uint32_t Bb,
                                       int wm, int wn, int l15, int lh8) {
    #pragma unroll
    for (int kk = 0; kk < 64; kk += 16) {
        uint32_t a[4][4];
        #pragma unroll
        for (int mf = 0; mf < 4; mf++)
            ldsm4(a[mf], Ab + ((wm + mf * 16 + l15) * 72 + kk + lh8) * 2);
        #pragma unroll
        for (int nb = 0; nb < 2; nb++) {
            uint32_t b[4];
            ldsm4t(b, Bb + ((kk + l15) * 136 + wn + nb * 16 + lh8) * 2);
            #pragma unroll
            for (int mf = 0; mf < 4; mf++) {
                mma_bf(acc[mf][nb * 2 + 0], a[mf], b + 0);
                mma_bf(acc[mf][nb * 2 + 1], a[mf], b + 2);
            }
        }
    }
}

// -------- generic GEMM (Wo / MLP) -------------------------------------------
template<int OUTF32>
__global__ __launch_bounds__(256, 2)
void gemm_bf(const bf16* __restrict__ A, const bf16* __restrict__ W,
             const float* __restrict__ bias,
             const bf16* __restrict__ residh, const float* __restrict__ residf,
             float* __restrict__ Cf, bf16* __restrict__ Ch,
             int M, int N, int K, int gelu) {
    extern __shared__ char smraw[];
    uint32_t smA = s2u(smraw);
    uint32_t smB = smA + 2 * GAB;
    int tid = threadIdx.x, lane = tid & 31, wid = tid >> 5;
    int m0 = blockIdx.y * 128, n0 = blockIdx.x * 128;
    int wm = (wid & 1) * 64, wn = (wid >> 1) * 32;

    float acc[4][4][4];
    #pragma unroll
    for (int i = 0; i < 4; i++)
        #pragma unroll
        for (int j = 0; j < 4; j++)
            #pragma unroll
            for (int k = 0; k < 4; k++) acc[i][j][k] = 0.f;

    g_stage(smA, smB, 0, A, W, m0, n0, 0, K, N, tid);
    int T = K >> 6, l15 = lane & 15, lh8 = (lane >> 4) << 3;

    for (int it = 0; it < T; it++) {
        cp_wait<0>();
        __syncthreads();
        if (it + 1 < T) g_stage(smA, smB, (it + 1) & 1, A, W, m0, n0, (it + 1) * 64, K, N, tid);
        g_tile(acc, smA + (it & 1) * GAB, smB + (it & 1) * GBB, wm, wn, l15, lh8);
        __syncthreads();
    }

    int r4 = lane >> 2, c2 = (lane & 3) * 2;
    #pragma unroll
    for (int mf = 0; mf < 4; mf++) {
        #pragma unroll
        for (int nf = 0; nf < 4; nf++) {
            int row = m0 + wm + mf * 16 + r4;
            int col = n0 + wn + nf * 8 + c2;
            float2 bi = *(const float2*)&bias[col];
            #pragma unroll
            for (int hh = 0; hh < 2; hh++) {
                int r = row + hh * 8;
                float v0 = acc[mf][nf][hh * 2 + 0] + bi.x;
                float v1 = acc[mf][nf][hh * 2 + 1] + bi.y;
                if (residh) {
                    uint32_t rp = *(const uint32_t*)&residh[(size_t)r * N + col];
                    float2 rr = __bfloat1622float2(*(__nv_bfloat162*)&rp);
                    v0 += rr.x; v1 += rr.y;
                }
                if (residf) {
                    float2 rr = *(const float2*)&residf[(size_t)r * N + col];
                    v0 += rr.x; v1 += rr.y;
                }
                if (gelu) {
                    v0 = 0.5f * v0 * (1.0f + erff(v0 * 0.70710678118654752f));
                    v1 = 0.5f * v1 * (1.0f + erff(v1 * 0.70710678118654752f));
                }
                if (OUTF32) *(float2*)&Cf[(size_t)r * N + col] = make_float2(v0, v1);
                else *(uint32_t*)&Ch[(size_t)r * N + col] = packbf(v0, v1);
            }
        }
    }
}

// -------- fused QKV GEMM: N=1536, split outputs ------------------------------
// A chosen per n-tile (cross-attn: Q cols read A1, K/V cols read A2).
__global__ __launch_bounds__(256, 2)
void gemm_qkv(const bf16* __restrict__ A1, const bf16* __restrict__ A2,
              const bf16* __restrict__ W, const float* __restrict__ bias,
              bf16* __restrict__ Oq, bf16* __restrict__ Ok, bf16* __restrict__ Ov) {
    const int K = DMODEL, N = 1536;
    extern __shared__ char smraw[];
    uint32_t smA = s2u(smraw);
    uint32_t smB = smA + 2 * GAB;
    int tid = threadIdx.x, lane = tid & 31, wid = tid >> 5;
    int m0 = blockIdx.y * 128, n0 = blockIdx.x * 128;
    const bf16* A = (n0 < 512) ? A1 : A2;
    int wm = (wid & 1) * 64, wn = (wid >> 1) * 32;

    float acc[4][4][4];
    #pragma unroll
    for (int i = 0; i < 4; i++)
        #pragma unroll
        for (int j = 0; j < 4; j++)
            #pragma unroll
            for (int k = 0; k < 4; k++) acc[i][j][k] = 0.f;

    g_stage(smA, smB, 0, A, W, m0, n0, 0, K, N, tid);
    int T = K >> 6, l15 = lane & 15, lh8 = (lane >> 4) << 3;

    for (int it = 0; it < T; it++) {
        cp_wait<0>();
        __syncthreads();
        if (it + 1 < T) g_stage(smA, smB, (it + 1) & 1, A, W, m0, n0, (it + 1) * 64, K, N, tid);
        g_tile(acc, smA + (it & 1) * GAB, smB + (it & 1) * GBB, wm, wn, l15, lh8);
        __syncthreads();
    }

    int r4 = lane >> 2, c2 = (lane & 3) * 2;
    #pragma unroll
    for (int mf = 0; mf < 4; mf++) {
        #pragma unroll
        for (int nf = 0; nf < 4; nf++) {
            int row = m0 + wm + mf * 16 + r4;
            int col = n0 + wn + nf * 8 + c2;
            bf16* dst = (col < 512) ? Oq : (col < 1024) ? Ok : Ov;
            int cc = col & 511;
            float2 bi = *(const float2*)&bias[col];
            #pragma unroll
            for (int hh = 0; hh < 2; hh++) {
                int r = row + hh * 8;
                float v0 = acc[mf][nf][hh * 2 + 0] + bi.x;
                float v1 = acc[mf][nf][hh * 2 + 1] + bi.y;
                *(uint32_t*)&dst[(size_t)r * DMODEL + cc] = packbf(v0, v1);
            }
        }
    }
}

// -------- bf16 flash attention (now 2 CTAs/SM) -------------------------------
#define AQB (128 * 272)
#define AKB (64 * 272)
#define AVB (64 * 272)
#define APB (128 * 144)
#define ATT_SMEM (AQB + 2 * AKB + AVB + APB)
#define NIT (SEQ / 64)

__global__ __launch_bounds__(256, 2)
void attn_bf(const bf16* __restrict__ Q, const bf16* __restrict__ K,
             const bf16* __restrict__ V, bf16* __restrict__ O) {
    extern __shared__ char smraw[];
    uint32_t smQ = s2u(smraw);
    uint32_t smK = smQ + AQB;
    uint32_t smV = smK + 2 * AKB;
    uint32_t smP = smV + AVB;
    bf16* Pp = (bf16*)(smraw + AQB + 2 * AKB + AVB);

    int tid = threadIdx.x, lane = tid & 31, wid = tid >> 5;
    int q0 = blockIdx.x * 128, h = blockIdx.y, b = blockIdx.z;
    size_t gq  = ((size_t)b * SEQ + q0) * DMODEL + (size_t)h * HDIM;
    size_t gk0 = ((size_t)b * SEQ) * DMODEL + (size_t)h * HDIM;
    int sr = tid >> 4, sg = tid & 15;

    #pragma unroll
    for (int i = 0; i < 8; i++) {
        int r = sr + 16 * i;
        cpa16(smQ + r * 272 + sg * 16, Q + gq + (size_t)r * DMODEL + sg * 8);
    }
    CP_COMMIT();
    #pragma unroll
    for (int i = 0; i < 4; i++) {
        int r = sr + 16 * i;
        cpa16(smK + r * 272 + sg * 16, K + gk0 + (size_t)r * DMODEL + sg * 8);
    }
    CP_COMMIT();
    #pragma unroll
    for (int i = 0; i < 4; i++) {
        int r = sr + 16 * i;
        cpa16(smV + r * 272 + sg * 16, V + gk0 + (size_t)r * DMODEL + sg * 8);
    }
    CP_COMMIT();
    cp_wait<0>();
    __syncthreads();

    float mrow[2] = {-1e30f, -1e30f}, lrow[2] = {0.f, 0.f};
    float o[16][4];
    #pragma unroll
    for (int i = 0; i < 16; i++)
        #pragma unroll
        for (int j = 0; j < 4; j++) o[i][j] = 0.f;

    int r4 = lane >> 2, c4 = lane & 3;
    int l15 = lane & 15, lh8 = (lane >> 4) << 3;
    int mq = wid * 16 + r4;

    for (int ic = 0; ic < NIT; ic++) {
        if (ic > 0) { cp_wait<1>(); __syncthreads(); }
        uint32_t Kb = smK + (ic & 1) * AKB;

        if (ic + 1 < NIT) {
            size_t gk = gk0 + (size_t)(ic + 1) * 64 * DMODEL;
            #pragma unroll
            for (int i = 0; i < 4; i++) {
                int r = sr + 16 * i;
                cpa16(smK + ((ic + 1) & 1) * AKB + r * 272 + sg * 16,
                      K + gk + (size_t)r * DMODEL + sg * 8);
            }
            CP_COMMIT();
        }

        float s[8][4];
        #pragma unroll
        for (int nf = 0; nf < 8; nf++)
            #pragma unroll
            for (int j = 0; j < 4; j++) s[nf][j] = 0.f;

        #pragma unroll
        for (int kd = 0; kd < 8; kd++) {
            uint32_t qa[4];
            ldsm4(qa, smQ + ((wid * 16 + l15) * 136 + kd * 16 + lh8) * 2);
            #pragma unroll
            for (int kb = 0; kb < 4; kb++) {
                uint32_t kf[4];
                ldsm4(kf, Kb + ((kb * 16 + (lane & 7) + lh8) * 136
                                + kd * 16 + (lane & 8)) * 2);
                mma_bf(s[kb * 2 + 0], qa, kf + 0);
                mma_bf(s[kb * 2 + 1], qa, kf + 2);
            }
        }

        #pragma unroll
        for (int h2 = 0; h2 < 2; h2++) {
            int base = h2 * 2;
            float mx = -1e30f;
            #pragma unroll
            for (int nf = 0; nf < 8; nf++)
                mx = fmaxf(mx, fmaxf(s[nf][base], s[nf][base + 1]));
            mx = fmaxf(mx, __shfl_xor_sync(0xffffffffu, mx, 1));
            mx = fmaxf(mx, __shfl_xor_sync(0xffffffffu, mx, 2));
            float mnew = fmaxf(mrow[h2], mx);
            float corr = __expf(mrow[h2] - mnew);
            mrow[h2] = mnew;
            int qrow = mq + 8 * h2;
            float ps = 0.f;
            #pragma unroll
            for (int nf = 0; nf < 8; nf++) {
                float p0 = __expf(s[nf][base]     - mnew);
                float p1 = __expf(s[nf][base + 1] - mnew);
                ps += p0 + p1;
                *(uint32_t*)&Pp[qrow * 72 + nf * 8 + 2 * c4] = packbf(p0, p1);
            }
            ps += __shfl_xor_sync(0xffffffffu, ps, 1);
            ps += __shfl_xor_sync(0xffffffffu, ps, 2);
            lrow[h2] = lrow[h2] * corr + ps;
            #pragma unroll
            for (int nf = 0; nf < 16; nf++) {
                o[nf][base]     *= corr;
                o[nf][base + 1] *= corr;
            }
        }
        __syncwarp();

        if (ic + 1 < NIT) cp_wait<1>(); else cp_wait<0>();
        __syncthreads();

        #pragma unroll
        for (int kc = 0; kc < 4; kc++) {
            uint32_t pa[4];
            ldsm4(pa, smP + ((wid * 16 + l15) * 72 + kc * 16 + lh8) * 2);
            #pragma unroll
            for (int nb = 0; nb < 8; nb++) {
                uint32_t vb[4];
                ldsm4t(vb, smV + ((kc * 16 + l15) * 136 + nb * 16 + lh8) * 2);
                mma_bf(o[nb * 2 + 0], pa, vb + 0);
                mma_bf(o[nb * 2 + 1], pa, vb + 2);
            }
        }
        __syncthreads();

        if (ic + 1 < NIT) {
            size_t gk = gk0 + (size_t)(ic + 1) * 64 * DMODEL;
            #pragma unroll
            for (int i = 0; i < 4; i++) {
                int r = sr + 16 * i;
                cpa16(smV + r * 272 + sg * 16, V + gk + (size_t)r * DMODEL + sg * 8);
            }
            CP_COMMIT();
        }
    }

    float inv0 = 1.0f / lrow[0], inv1 = 1.0f / lrow[1];
    #pragma unroll
    for (int nf = 0; nf < 16; nf++) {
        int col = nf * 8 + 2 * c4;
        size_t base0 = gq + (size_t)mq * DMODEL + col;
        *(uint32_t*)&O[base0]              = packbf(o[nf][0] * inv0, o[nf][1] * inv0);
        *(uint32_t*)&O[base0 + 8 * DMODEL] = packbf(o[nf][2] * inv1, o[nf][3] * inv1);
    }
}

// -------- driver -------------------------------------------------------------
extern "C" void kernel_launch(void* const* d_in, const int* in_sizes, int n_in,
                              void* d_out, int out_size) {
    const float* x1    = (const float*)d_in[0];
    const float* x2    = (const float*)d_in[1];
    const float* ln1_g = (const float*)d_in[2];
    const float* ln1_b = (const float*)d_in[3];
    const float* ln2_g = (const float*)d_in[4];
    const float* ln2_b = (const float*)d_in[5];
    const float* lnf_g = (const float*)d_in[6];
    const float* lnf_b = (const float*)d_in[7];
    const float* bo    = (const float*)d_in[27];
    const float* b1    = (const float*)d_in[29];
    const float* b2    = (const float*)d_in[31];
    float* out = (float*)d_out;

    bf16 *x1n, *x2n, *q, *k, *v, *ctx, *src1, *src2, *hbuf, *wr;
    float *xres, *bqkv;
    cudaGetSymbolAddress((void**)&x1n,  g_x1n);
    cudaGetSymbolAddress((void**)&x2n,  g_x2n);
    cudaGetSymbolAddress((void**)&q,    g_q);
    cudaGetSymbolAddress((void**)&k,    g_k);
    cudaGetSymbolAddress((void**)&v,    g_v);
    cudaGetSymbolAddress((void**)&ctx,  g_ctx);
    cudaGetSymbolAddress((void**)&src1, g_src1);
    cudaGetSymbolAddress((void**)&src2, g_src2);
    cudaGetSymbolAddress((void**)&xres, g_xres);
    cudaGetSymbolAddress((void**)&hbuf, g_h);
    cudaGetSymbolAddress((void**)&wr,   g_wr);
    cudaGetSymbolAddress((void**)&bqkv, g_bqkv);

    const bf16* Wqkv1  = wr;
    const bf16* Wqkv2  = wr + 786432;
    const bf16* Wqkv12 = wr + 1572864;
    const bf16* Wor    = wr + 2359296;
    const bf16* W1r    = wr + 2621440;
    const bf16* W2r    = wr + 3145728;

    cudaFuncSetAttribute(gemm_bf<0>, cudaFuncAttributeMaxDynamicSharedMemorySize, GEMM_SMEM);
    cudaFuncSetAttribute(gemm_bf<1>, cudaFuncAttributeMaxDynamicSharedMemorySize, GEMM_SMEM);
    cudaFuncSetAttribute(gemm_qkv,   cudaFuncAttributeMaxDynamicSharedMemorySize, GEMM_SMEM);
    cudaFuncSetAttribute(attn_bf,    cudaFuncAttributeMaxDynamicSharedMemorySize, ATT_SMEM);

    dim3 gAttn(SEQ / 128, NHEAD, BATCH);
    dim3 gQKV (12, MROWS / 128);
    dim3 g512 (4,  MROWS / 128);
    dim3 g1024(8,  MROWS / 128);
    const float qs = 0.08838834764831845f;

    WPtrs wp;
    wp.s[0] = (const float*)d_in[8];  wp.s[1] = (const float*)d_in[10];
    wp.s[2] = (const float*)d_in[12]; wp.s[3] = (const float*)d_in[14];
    wp.s[4] = (const float*)d_in[16]; wp.s[5] = (const float*)d_in[18];
    wp.s[6] = (const float*)d_in[20]; wp.s[7] = (const float*)d_in[22];
    wp.s[8] = (const float*)d_in[24]; wp.s[9] = (const float*)d_in[26];
    wp.s[10] = (const float*)d_in[28]; wp.s[11] = (const float*)d_in[30];
    round_w<<<1792, 256>>>(wp, wr, qs);

    BPtrs bp;
    bp.s[0] = (const float*)d_in[9];  bp.s[1] = (const float*)d_in[11];
    bp.s[2] = (const float*)d_in[13]; bp.s[3] = (const float*)d_in[15];
    bp.s[4] = (const float*)d_in[17]; bp.s[5] = (const float*)d_in[19];
    bp.s[6] = (const float*)d_in[21]; bp.s[7] = (const float*)d_in[23];
    bp.s[8] = (const float*)d_in[25];
    round_b<<<18, 256>>>(bp, bqkv, qs);

    ln_kernel<<<MROWS, 128>>>(x1, ln1_g, ln1_b, x1n);
    ln_kernel<<<MROWS, 128>>>(x2, ln2_g, ln2_b, x2n);

    // stream-1 self-attention
    gemm_qkv<<<gQKV, 256, GEMM_SMEM>>>(x1n, x1n, Wqkv1, bqkv, q, k, v);
    attn_bf<<<gAttn, 256, ATT_SMEM>>>(q, k, v, ctx);
    gemm_bf<0><<<g512, 256, GEMM_SMEM>>>(ctx, Wor, bo, x1n, nullptr, nullptr, src1,
                                         MROWS, DMODEL, DMODEL, 0);

    // stream-2 self-attention
    gemm_qkv<<<gQKV, 256, GEMM_SMEM>>>(x2n, x2n, Wqkv2, bqkv + 1536, q, k, v);
    attn_bf<<<gAttn, 256, ATT_SMEM>>>(q, k, v, ctx);
    gemm_bf<0><<<g512, 256, GEMM_SMEM>>>(ctx, Wor, bo, x2n, nullptr, nullptr, src2,
                                         MROWS, DMODEL, DMODEL, 0);

    // cross attention: Q cols from src1, K/V cols from src2
    gemm_qkv<<<gQKV, 256, GEMM_SMEM>>>(src1, src2, Wqkv12, bqkv + 3072, q, k, v);
    attn_bf<<<gAttn, 256, ATT_SMEM>>>(q, k, v, ctx);
    gemm_bf<1><<<g512, 256, GEMM_SMEM>>>(ctx, Wor, bo, nullptr, x1, xres, nullptr,
                                         MROWS, DMODEL, DMODEL, 0);

    // final LN + MLP
    ln_kernel<<<MROWS, 128>>>(xres, lnf_g, lnf_b, x1n);
    gemm_bf<0><<<g1024, 256, GEMM_SMEM>>>(x1n, W1r, b1, nullptr, nullptr, nullptr, hbuf,
                                          MROWS, DMLP, DMODEL, 1);
    gemm_bf<1><<<g512, 256, GEMM_SMEM>>>(hbuf, W2r, b2, nullptr, xres, out, nullptr,
                                         MROWS, DMODEL, DMLP, 0);
}

// round 7
// speedup vs baseline: 1.9316x; 1.0152x over previous
#include <cuda_runtime.h>
#include <cuda_bf16.h>
#include <math.h>
#include <stdint.h>

#define BATCH 16
#define SEQ   1024
#define DMODEL 512
#define NHEAD 4
#define HDIM  128
#define MROWS (BATCH * SEQ)
#define DMLP  1024

typedef __nv_bfloat16 bf16;

__device__ bf16  g_x1n [MROWS * DMODEL];
__device__ bf16  g_x2n [MROWS * DMODEL];
__device__ bf16  g_q1  [MROWS * DMODEL];
__device__ bf16  g_k1  [MROWS * DMODEL];
__device__ bf16  g_v1  [MROWS * DMODEL];
__device__ bf16  g_q2  [MROWS * DMODEL];
__device__ bf16  g_k2  [MROWS * DMODEL];
__device__ bf16  g_v2  [MROWS * DMODEL];
__device__ bf16  g_ctx1[MROWS * DMODEL];
__device__ bf16  g_ctx2[MROWS * DMODEL];
__device__ bf16  g_src1[MROWS * DMODEL];
__device__ bf16  g_src2[MROWS * DMODEL];
__device__ float g_xres[MROWS * DMODEL];
__device__ bf16  g_h   [MROWS * DMLP];
__device__ bf16  g_wr  [3670016];
__device__ float g_bqkv[4608];

__device__ __forceinline__ uint32_t s2u(const void* p) {
    return (uint32_t)__cvta_generic_to_shared(p);
}
__device__ __forceinline__ void cpa16(uint32_t dst, const void* src) {
    asm volatile("cp.async.cg.shared.global [%0], [%1], 16;" :: "r"(dst), "l"(src));
}
#define CP_COMMIT() asm volatile("cp.async.commit_group;")
template <int N> __device__ __forceinline__ void cp_wait() {
    asm volatile("cp.async.wait_group %0;" :: "n"(N));
}
__device__ __forceinline__ void ldsm4(uint32_t* r, uint32_t a) {
    asm volatile("ldmatrix.sync.aligned.m8n8.x4.shared.b16 {%0,%1,%2,%3}, [%4];"
                 : "=r"(r[0]), "=r"(r[1]), "=r"(r[2]), "=r"(r[3]) : "r"(a));
}
__device__ __forceinline__ void ldsm4t(uint32_t* r, uint32_t a) {
    asm volatile("ldmatrix.sync.aligned.m8n8.x4.trans.shared.b16 {%0,%1,%2,%3}, [%4];"
                 : "=r"(r[0]), "=r"(r[1]), "=r"(r[2]), "=r"(r[3]) : "r"(a));
}
__device__ __forceinline__ void mma_bf(float* c, const uint32_t* a, const uint32_t* b) {
    asm volatile(
        "mma.sync.aligned.m16n8k16.row.col.f32.bf16.bf16.f32 "
        "{%0,%1,%2,%3}, {%4,%5,%6,%7}, {%8,%9}, {%0,%1,%2,%3};"
        : "+f"(c[0]), "+f"(c[1]), "+f"(c[2]), "+f"(c[3])
        : "r"(a[0]), "r"(a[1]), "r"(a[2]), "r"(a[3]), "r"(b[0]), "r"(b[1]));
}
__device__ __forceinline__ uint32_t packbf(float x, float y) {
    __nv_bfloat162 h = __floats2bfloat162_rn(x, y);
    return *(uint32_t*)&h;
}

// -------- weight repack ------------------------------------------------------
struct WPtrs { const float* s[12]; };
__global__ void round_w(WPtrs p, bf16* dst, float qs) {
    int t = blockIdx.x * blockDim.x + threadIdx.x;
    int idx = t * 8;
    if (idx >= 3670016) return;
    const float* src; float sc = 1.f; int off;
    if (idx < 2359296) {
        int s = idx / 786432, rem = idx % 786432;
        int kk = rem / 1536, n = rem % 1536;
        int m = n >> 9;
        src = p.s[s * 3 + m];
        off = kk * 512 + (n & 511);
        if (m == 0) sc = qs;
    } else if (idx < 2621440) { src = p.s[9];  off = idx - 2359296; }
    else if (idx < 3145728)   { src = p.s[10]; off = idx - 2621440; }
    else                      { src = p.s[11]; off = idx - 3145728; }
    float4 v0 = *(const float4*)&src[off];
    float4 v1 = *(const float4*)&src[off + 4];
    uint32_t h[4] = { packbf(v0.x*sc, v0.y*sc), packbf(v0.z*sc, v0.w*sc),
                      packbf(v1.x*sc, v1.y*sc), packbf(v1.z*sc, v1.w*sc) };
    *(uint4*)&dst[idx] = *(uint4*)h;
}

struct BPtrs { const float* s[9]; };
__global__ void round_b(BPtrs p, float* dst, float qs) {
    int i = blockIdx.x * blockDim.x + threadIdx.x;
    if (i >= 4608) return;
    int s = i / 1536, n = i % 1536, m = n >> 9;
    float v = p.s[s * 3 + m][n & 511];
    dst[i] = (m == 0) ? v * qs : v;
}

// -------- dual LayerNorm -----------------------------------------------------
struct LnA { const float* x[2]; const float* g[2]; const float* b[2]; bf16* y[2]; };
__global__ void ln2_kernel(LnA a) {
    int row = blockIdx.x, t = threadIdx.x;
    int si = row >> 14; row &= (MROWS - 1);
    const float* xr = a.x[si] + (size_t)row * DMODEL;
    float4 v4 = ((const float4*)xr)[t];
    __shared__ float red[4];
    float s = v4.x + v4.y + v4.z + v4.w;
    #pragma unroll
    for (int o = 16; o; o >>= 1) s += __shfl_xor_sync(0xffffffffu, s, o);
    if ((t & 31) == 0) red[t >> 5] = s;
    __syncthreads();
    float mean = (red[0] + red[1] + red[2] + red[3]) * (1.0f / DMODEL);
    __syncthreads();
    float dx = v4.x - mean, dy = v4.y - mean, dz = v4.z - mean, dw = v4.w - mean;
    float vs = dx*dx + dy*dy + dz*dz + dw*dw;
    #pragma unroll
    for (int o = 16; o; o >>= 1) vs += __shfl_xor_sync(0xffffffffu, vs, o);
    if ((t & 31) == 0) red[t >> 5] = vs;
    __syncthreads();
    float var = (red[0] + red[1] + red[2] + red[3]) * (1.0f / DMODEL);
    float inv = rsqrtf(var + 1e-6f);
    float4 g4 = ((const float4*)a.g[si])[t];
    float4 b4 = ((const float4*)a.b[si])[t];
    uint32_t h[2] = { packbf(dx * inv * g4.x + b4.x, dy * inv * g4.y + b4.y),
                      packbf(dz * inv * g4.z + b4.z, dw * inv * g4.w + b4.w) };
    *(uint2*)&a.y[si][(size_t)row * DMODEL + t * 4] = *(uint2*)h;
}

// -------- GEMM tile machinery (BK=64) ---------------------------------------
#define GAB (128 * 144)
#define GBB (64 * 272)
#define GEMM_SMEM (2 * (GAB + GBB))

__device__ __forceinline__ void g_stage(uint32_t smA, uint32_t smB, int buf,
                                        const bf16* A, const bf16* W,
                                        int m0, int n0, int k0, int K, int N, int tid) {
    int ar = tid >> 1, ag = (tid & 1) * 4;
    uint32_t da = smA + buf * GAB + ar * 144 + ag * 16;
    const bf16* sa = A + (size_t)(m0 + ar) * K + k0 + ag * 8;
    #pragma unroll
    for (int i = 0; i < 4; i++) cpa16(da + i * 16, sa + i * 8);
    int br = tid >> 2, bg = (tid & 3) * 4;
    uint32_t db = smB + buf * GBB + br * 272 + bg * 16;
    const bf16* sb = W + (size_t)(k0 + br) * N + n0 + bg * 8;
    #pragma unroll
    for (int i = 0; i < 4; i++) cpa16(db + i * 16, sb + i * 8);
    CP_COMMIT();
}

__device__ __forceinline__ void g_tile(float acc[4][4][4], uint32_t Ab, uint32_t Bb,
                                       int wm, int wn, int l15, int lh8) {
    #pragma unroll
    for (int kk = 0; kk < 64; kk += 16) {
        uint32_t a[4][4];
        #pragma unroll
        for (int mf = 0; mf < 4; mf++)
            ldsm4(a[mf], Ab + ((wm + mf * 16 + l15) * 72 + kk + lh8) * 2);
        #pragma unroll
        for (int nb = 0; nb < 2; nb++) {
            uint32_t b[4];
            ldsm4t(b, Bb + ((kk + l15) * 136 + wn + nb * 16 + lh8) * 2);
            #pragma unroll
            for (int mf = 0; mf < 4; mf++) {
                mma_bf(acc[mf][nb * 2 + 0], a[mf], b + 0);
                mma_bf(acc[mf][nb * 2 + 1], a[mf], b + 2);
            }
        }
    }
}

#define G_PROLOG_COMPUTE(Aptr, Wptr, Nval, Kval)                               \
    float acc[4][4][4];                                                        \
    _Pragma("unroll")                                                          \
    for (int i = 0; i < 4; i++)                                                \
        _Pragma("unroll")                                                      \
        for (int j = 0; j < 4; j++)                                            \
            _Pragma("unroll")                                                  \
            for (int kq = 0; kq < 4; kq++) acc[i][j][kq] = 0.f;                \
    g_stage(smA, smB, 0, Aptr, Wptr, m0, n0, 0, Kval, Nval, tid);              \
    int T = (Kval) >> 6, l15 = lane & 15, lh8 = (lane >> 4) << 3;              \
    for (int it = 0; it < T; it++) {                                           \
        cp_wait<0>();                                                          \
        __syncthreads();                                                       \
        if (it + 1 < T)                                                        \
            g_stage(smA, smB, (it + 1) & 1, Aptr, Wptr, m0, n0,                \
                    (it + 1) * 64, Kval, Nval, tid);                           \
        g_tile(acc, smA + (it & 1) * GAB, smB + (it & 1) * GBB,                \
               wm, wn, l15, lh8);                                              \
        __syncthreads();                                                       \
    }

// -------- generic GEMM (MLP / cross-Wo) -------------------------------------
template<int OUTF32>
__global__ __launch_bounds__(256, 2)
void gemm_bf(const bf16* __restrict__ A, const bf16* __restrict__ W,
             const float* __restrict__ bias,
             const bf16* __restrict__ residh, const float* __restrict__ residf,
             float* __restrict__ Cf, bf16* __restrict__ Ch,
             int M, int N, int K, int gelu) {
    extern __shared__ char smraw[];
    uint32_t smA = s2u(smraw);
    uint32_t smB = smA + 2 * GAB;
    int tid = threadIdx.x, lane = tid & 31, wid = tid >> 5;
    int m0 = blockIdx.y * 128, n0 = blockIdx.x * 128;
    int wm = (wid & 1) * 64, wn = (wid >> 1) * 32;

    G_PROLOG_COMPUTE(A, W, N, K)

    int r4 = lane >> 2, c2 = (lane & 3) * 2;
    #pragma unroll
    for (int mf = 0; mf < 4; mf++) {
        #pragma unroll
        for (int nf = 0; nf < 4; nf++) {
            int row = m0 + wm + mf * 16 + r4;
            int col = n0 + wn + nf * 8 + c2;
            float2 bi = *(const float2*)&bias[col];
            #pragma unroll
            for (int hh = 0; hh < 2; hh++) {
                int r = row + hh * 8;
                float v0 = acc[mf][nf][hh * 2 + 0] + bi.x;
                float v1 = acc[mf][nf][hh * 2 + 1] + bi.y;
                if (residh) {
                    uint32_t rp = *(const uint32_t*)&residh[(size_t)r * N + col];
                    float2 rr = __bfloat1622float2(*(__nv_bfloat162*)&rp);
                    v0 += rr.x; v1 += rr.y;
                }
                if (residf) {
                    float2 rr = *(const float2*)&residf[(size_t)r * N + col];
                    v0 += rr.x; v1 += rr.y;
                }
                if (gelu) {
                    v0 = 0.5f * v0 * (1.0f + erff(v0 * 0.70710678118654752f));
                    v1 = 0.5f * v1 * (1.0f + erff(v1 * 0.70710678118654752f));
                }
                if (OUTF32) *(float2*)&Cf[(size_t)r * N + col] = make_float2(v0, v1);
                else *(uint32_t*)&Ch[(size_t)r * N + col] = packbf(v0, v1);
            }
        }
    }
}

// -------- fused QKV GEMM, dual-stream ----------------------------------------
struct QkvA {
    const bf16* Aq[2]; const bf16* Akv[2]; const bf16* W[2];
    const float* bias[2]; bf16* q[2]; bf16* k[2]; bf16* v[2];
};
__global__ __launch_bounds__(256, 2)
void gemm_qkv(QkvA p) {
    const int K = DMODEL, N = 1536;
    extern __shared__ char smraw[];
    uint32_t smA = s2u(smraw);
    uint32_t smB = smA + 2 * GAB;
    int tid = threadIdx.x, lane = tid & 31, wid = tid >> 5;
    int nb12 = blockIdx.x;
    int si = nb12 / 12;
    int n0 = (nb12 % 12) * 128, m0 = blockIdx.y * 128;
    const bf16* A = (n0 < 512) ? p.Aq[si] : p.Akv[si];
    const bf16* W = p.W[si];
    int wm = (wid & 1) * 64, wn = (wid >> 1) * 32;

    G_PROLOG_COMPUTE(A, W, N, K)

    int r4 = lane >> 2, c2 = (lane & 3) * 2;
    #pragma unroll
    for (int mf = 0; mf < 4; mf++) {
        #pragma unroll
        for (int nf = 0; nf < 4; nf++) {
            int row = m0 + wm + mf * 16 + r4;
            int col = n0 + wn + nf * 8 + c2;
            bf16* dst = (col < 512) ? p.q[si] : (col < 1024) ? p.k[si] : p.v[si];
            int cc = col & 511;
            float2 bi = *(const float2*)&p.bias[si][col];
            #pragma unroll
            for (int hh = 0; hh < 2; hh++) {
                int r = row + hh * 8;
                float v0 = acc[mf][nf][hh * 2 + 0] + bi.x;
                float v1 = acc[mf][nf][hh * 2 + 1] + bi.y;
                *(uint32_t*)&dst[(size_t)r * DMODEL + cc] = packbf(v0, v1);
            }
        }
    }
}

// -------- fused Wo GEMM, dual-stream (bf16 out + bf16 resid) -----------------
struct WoA { const bf16* A[2]; const bf16* resid[2]; bf16* out[2]; };
__global__ __launch_bounds__(256, 2)
void gemm_wo(WoA p, const bf16* __restrict__ W, const float* __restrict__ bias) {
    const int K = DMODEL, N = DMODEL;
    extern __shared__ char smraw[];
    uint32_t smA = s2u(smraw);
    uint32_t smB = smA + 2 * GAB;
    int tid = threadIdx.x, lane = tid & 31, wid = tid >> 5;
    int si = blockIdx.x >> 2;
    int n0 = (blockIdx.x & 3) * 128, m0 = blockIdx.y * 128;
    const bf16* A = p.A[si];
    int wm = (wid & 1) * 64, wn = (wid >> 1) * 32;

    G_PROLOG_COMPUTE(A, W, N, K)

    int r4 = lane >> 2, c2 = (lane & 3) * 2;
    #pragma unroll
    for (int mf = 0; mf < 4; mf++) {
        #pragma unroll
        for (int nf = 0; nf < 4; nf++) {
            int row = m0 + wm + mf * 16 + r4;
            int col = n0 + wn + nf * 8 + c2;
            float2 bi = *(const float2*)&bias[col];
            #pragma unroll
            for (int hh = 0; hh < 2; hh++) {
                int r = row + hh * 8;
                uint32_t rp = *(const uint32_t*)&p.resid[si][(size_t)r * N + col];
                float2 rr = __bfloat1622float2(*(__nv_bfloat162*)&rp);
                float v0 = acc[mf][nf][hh * 2 + 0] + bi.x + rr.x;
                float v1 = acc[mf][nf][hh * 2 + 1] + bi.y + rr.y;
                *(uint32_t*)&p.out[si][(size_t)r * N + col] = packbf(v0, v1);
            }
        }
    }
}

// -------- bf16 flash attention: register P, K+V double-buffered --------------
#define AQB (128 * 272)
#define AKB (64 * 272)
#define AVB (64 * 272)
#define ATT_SMEM (AQB + 2 * AKB + 2 * AVB)
#define NIT (SEQ / 64)

struct AttA { const bf16* Q[2]; const bf16* K[2]; const bf16* V[2]; bf16* O[2]; };
__global__ __launch_bounds__(256, 2)
void attn_bf(AttA p) {
    extern __shared__ char smraw[];
    uint32_t smQ = s2u(smraw);
    uint32_t smK = smQ + AQB;
    uint32_t smV = smK + 2 * AKB;

    int tid = threadIdx.x, lane = tid & 31, wid = tid >> 5;
    int q0 = blockIdx.x * 128, h = blockIdx.y;
    int zi = blockIdx.z;
    int si = zi >> 4, b = zi & 15;
    const bf16* Q = p.Q[si];
    const bf16* K = p.K[si];
    const bf16* V = p.V[si];
    bf16* O = p.O[si];
    size_t gq  = ((size_t)b * SEQ + q0) * DMODEL + (size_t)h * HDIM;
    size_t gk0 = ((size_t)b * SEQ) * DMODEL + (size_t)h * HDIM;
    int sr = tid >> 4, sg = tid & 15;

    #pragma unroll
    for (int i = 0; i < 8; i++) {
        int r = sr + 16 * i;
        cpa16(smQ + r * 272 + sg * 16, Q + gq + (size_t)r * DMODEL + sg * 8);
    }
    CP_COMMIT();
    #pragma unroll
    for (int i = 0; i < 4; i++) {
        int r = sr + 16 * i;
        cpa16(smK + r * 272 + sg * 16, K + gk0 + (size_t)r * DMODEL + sg * 8);
        cpa16(smV + r * 272 + sg * 16, V + gk0 + (size_t)r * DMODEL + sg * 8);
    }
    CP_COMMIT();
    cp_wait<0>();
    __syncthreads();

    float mrow[2] = {-1e30f, -1e30f}, lrow[2] = {0.f, 0.f};
    float o[16][4];
    #pragma unroll
    for (int i = 0; i < 16; i++)
        #pragma unroll
        for (int j = 0; j < 4; j++) o[i][j] = 0.f;

    int l15 = lane & 15, lh8 = (lane >> 4) << 3;

    for (int ic = 0; ic < NIT; ic++) {
        if (ic > 0) { cp_wait<0>(); __syncthreads(); }
        uint32_t Kb = smK + (ic & 1) * AKB;
        uint32_t Vb = smV + (ic & 1) * AVB;

        if (ic + 1 < NIT) {
            size_t gk = gk0 + (size_t)(ic + 1) * 64 * DMODEL;
            uint32_t ko = smK + ((ic + 1) & 1) * AKB;
            uint32_t vo = smV + ((ic + 1) & 1) * AVB;
            #pragma unroll
            for (int i = 0; i < 4; i++) {
                int r = sr + 16 * i;
                cpa16(ko + r * 272 + sg * 16, K + gk + (size_t)r * DMODEL + sg * 8);
                cpa16(vo + r * 272 + sg * 16, V + gk + (size_t)r * DMODEL + sg * 8);
            }
            CP_COMMIT();
        }

        // S = Q @ K^T  (16 x 64 per warp)
        float s[8][4];
        #pragma unroll
        for (int nf = 0; nf < 8; nf++)
            #pragma unroll
            for (int j = 0; j < 4; j++) s[nf][j] = 0.f;

        #pragma unroll
        for (int kd = 0; kd < 8; kd++) {
            uint32_t qa[4];
            ldsm4(qa, smQ + ((wid * 16 + l15) * 136 + kd * 16 + lh8) * 2);
            #pragma unroll
            for (int kb = 0; kb < 4; kb++) {
                uint32_t kf[4];
                ldsm4(kf, Kb + ((kb * 16 + (lane & 7) + lh8) * 136
                                + kd * 16 + (lane & 8)) * 2);
                mma_bf(s[kb * 2 + 0], qa, kf + 0);
                mma_bf(s[kb * 2 + 1], qa, kf + 2);
            }
        }

        // online softmax; exp(S) stays in registers as P
        #pragma unroll
        for (int h2 = 0; h2 < 2; h2++) {
            int base = h2 * 2;
            float mx = -1e30f;
            #pragma unroll
            for (int nf = 0; nf < 8; nf++)
                mx = fmaxf(mx, fmaxf(s[nf][base], s[nf][base + 1]));
            mx = fmaxf(mx, __shfl_xor_sync(0xffffffffu, mx, 1));
            mx = fmaxf(mx, __shfl_xor_sync(0xffffffffu, mx, 2));
            float mnew = fmaxf(mrow[h2], mx);
            float corr = __expf(mrow[h2] - mnew);
            mrow[h2] = mnew;
            float ps = 0.f;
            #pragma unroll
            for (int nf = 0; nf < 8; nf++) {
                float p0 = __expf(s[nf][base]     - mnew);
                float p1 = __expf(s[nf][base + 1] - mnew);
                s[nf][base] = p0; s[nf][base + 1] = p1;
                ps += p0 + p1;
            }
            ps += __shfl_xor_sync(0xffffffffu, ps, 1);
            ps += __shfl_xor_sync(0xffffffffu, ps, 2);
            lrow[h2] = lrow[h2] * corr + ps;
            #pragma unroll
            for (int nf = 0; nf < 16; nf++) {
                o[nf][base]     *= corr;
                o[nf][base + 1] *= corr;
            }
        }

        // O += P @ V  (P fragments built directly from S registers)
        #pragma unroll
        for (int kc = 0; kc < 4; kc++) {
            uint32_t pa[4] = {
                packbf(s[2 * kc][0],     s[2 * kc][1]),
                packbf(s[2 * kc][2],     s[2 * kc][3]),
                packbf(s[2 * kc + 1][0], s[2 * kc + 1][1]),
                packbf(s[2 * kc + 1][2], s[2 * kc + 1][3]) };
            #pragma unroll
            for (int nb = 0; nb < 8; nb++) {
                uint32_t vb[4];
                ldsm4t(vb, Vb + ((kc * 16 + l15) * 136 + nb * 16 + lh8) * 2);
                mma_bf(o[nb * 2 + 0], pa, vb + 0);
                mma_bf(o[nb * 2 + 1], pa, vb + 2);
            }
        }
    }

    int r4 = lane >> 2, c4 = lane & 3;
    int mq = wid * 16 + r4;
    float inv0 = 1.0f / lrow[0], inv1 = 1.0f / lrow[1];
    #pragma unroll
    for (int nf = 0; nf < 16; nf++) {
        int col = nf * 8 + 2 * c4;
        size_t base0 = gq + (size_t)mq * DMODEL + col;
        *(uint32_t*)&O[base0]              = packbf(o[nf][0] * inv0, o[nf][1] * inv0);
        *(uint32_t*)&O[base0 + 8 * DMODEL] = packbf(o[nf][2] * inv1, o[nf][3] * inv1);
    }
}

// -------- driver -------------------------------------------------------------
extern "C" void kernel_launch(void* const* d_in, const int* in_sizes, int n_in,
                              void* d_out, int out_size) {
    const float* x1    = (const float*)d_in[0];
    const float* x2    = (const float*)d_in[1];
    const float* lnf_g = (const float*)d_in[6];
    const float* lnf_b = (const float*)d_in[7];
    const float* bo    = (const float*)d_in[27];
    const float* b1    = (const float*)d_in[29];
    const float* b2    = (const float*)d_in[31];
    float* out = (float*)d_out;

    bf16 *x1n, *x2n, *q1, *k1, *v1, *q2, *k2, *v2, *ctx1, *ctx2, *src1, *src2, *hbuf, *wr;
    float *xres, *bqkv;
    cudaGetSymbolAddress((void**)&x1n,  g_x1n);
    cudaGetSymbolAddress((void**)&x2n,  g_x2n);
    cudaGetSymbolAddress((void**)&q1,   g_q1);
    cudaGetSymbolAddress((void**)&k1,   g_k1);
    cudaGetSymbolAddress((void**)&v1,   g_v1);
    cudaGetSymbolAddress((void**)&q2,   g_q2);
    cudaGetSymbolAddress((void**)&k2,   g_k2);
    cudaGetSymbolAddress((void**)&v2,   g_v2);
    cudaGetSymbolAddress((void**)&ctx1, g_ctx1);
    cudaGetSymbolAddress((void**)&ctx2, g_ctx2);
    cudaGetSymbolAddress((void**)&src1, g_src1);
    cudaGetSymbolAddress((void**)&src2, g_src2);
    cudaGetSymbolAddress((void**)&xres, g_xres);
    cudaGetSymbolAddress((void**)&hbuf, g_h);
    cudaGetSymbolAddress((void**)&wr,   g_wr);
    cudaGetSymbolAddress((void**)&bqkv, g_bqkv);

    const bf16* Wqkv1  = wr;
    const bf16* Wqkv2  = wr + 786432;
    const bf16* Wqkv12 = wr + 1572864;
    const bf16* Wor    = wr + 2359296;
    const bf16* W1r    = wr + 2621440;
    const bf16* W2r    = wr + 3145728;

    cudaFuncSetAttribute(gemm_bf<0>, cudaFuncAttributeMaxDynamicSharedMemorySize, GEMM_SMEM);
    cudaFuncSetAttribute(gemm_bf<1>, cudaFuncAttributeMaxDynamicSharedMemorySize, GEMM_SMEM);
    cudaFuncSetAttribute(gemm_qkv,   cudaFuncAttributeMaxDynamicSharedMemorySize, GEMM_SMEM);
    cudaFuncSetAttribute(gemm_wo,    cudaFuncAttributeMaxDynamicSharedMemorySize, GEMM_SMEM);
    cudaFuncSetAttribute(attn_bf,    cudaFuncAttributeMaxDynamicSharedMemorySize, ATT_SMEM);

    const float qs = 0.08838834764831845f;

    WPtrs wp;
    wp.s[0] = (const float*)d_in[8];  wp.s[1] = (const float*)d_in[10];
    wp.s[2] = (const float*)d_in[12]; wp.s[3] = (const float*)d_in[14];
    wp.s[4] = (const float*)d_in[16]; wp.s[5] = (const float*)d_in[18];
    wp.s[6] = (const float*)d_in[20]; wp.s[7] = (const float*)d_in[22];
    wp.s[8] = (const float*)d_in[24]; wp.s[9] = (const float*)d_in[26];
    wp.s[10] = (const float*)d_in[28]; wp.s[11] = (const float*)d_in[30];
    round_w<<<1792, 256>>>(wp, wr, qs);

    BPtrs bp;
    bp.s[0] = (const float*)d_in[9];  bp.s[1] = (const float*)d_in[11];
    bp.s[2] = (const float*)d_in[13]; bp.s[3] = (const float*)d_in[15];
    bp.s[4] = (const float*)d_in[17]; bp.s[5] = (const float*)d_in[19];
    bp.s[6] = (const float*)d_in[21]; bp.s[7] = (const float*)d_in[23];
    bp.s[8] = (const float*)d_in[25];
    round_b<<<18, 256>>>(bp, bqkv, qs);

    // both LNs in one launch
    LnA la;
    la.x[0] = x1; la.x[1] = x2;
    la.g[0] = (const float*)d_in[2]; la.g[1] = (const float*)d_in[4];
    la.b[0] = (const float*)d_in[3]; la.b[1] = (const float*)d_in[5];
    la.y[0] = x1n; la.y[1] = x2n;
    ln2_kernel<<<2 * MROWS, 128>>>(la);

    // fused dual-stream QKV
    QkvA qa;
    qa.Aq[0] = x1n; qa.Akv[0] = x1n; qa.W[0] = Wqkv1; qa.bias[0] = bqkv;
    qa.q[0] = q1; qa.k[0] = k1; qa.v[0] = v1;
    qa.Aq[1] = x2n; qa.Akv[1] = x2n; qa.W[1] = Wqkv2; qa.bias[1] = bqkv + 1536;
    qa.q[1] = q2; qa.k[1] = k2; qa.v[1] = v2;
    gemm_qkv<<<dim3(24, MROWS / 128), 256, GEMM_SMEM>>>(qa);

    // fused dual-stream attention
    AttA aa;
    aa.Q[0] = q1; aa.K[0] = k1; aa.V[0] = v1; aa.O[0] = ctx1;
    aa.Q[1] = q2; aa.K[1] = k2; aa.V[1] = v2; aa.O[1] = ctx2;
    attn_bf<<<dim3(SEQ / 128, NHEAD, 2 * BATCH), 256, ATT_SMEM>>>(aa);

    // fused dual-stream Wo + residual
    WoA wo;
    wo.A[0] = ctx1; wo.resid[0] = x1n; wo.out[0] = src1;
    wo.A[1] = ctx2; wo.resid[1] = x2n; wo.out[1] = src2;
    gemm_wo<<<dim3(8, MROWS / 128), 256, GEMM_SMEM>>>(wo, Wor, bo);

    // cross attention
    QkvA qc;
    qc.Aq[0] = src1; qc.Akv[0] = src2; qc.W[0] = Wqkv12; qc.bias[0] = bqkv + 3072;
    qc.q[0] = q1; qc.k[0] = k1; qc.v[0] = v1;
    qc.Aq[1] = src1; qc.Akv[1] = src2; qc.W[1] = Wqkv12; qc.bias[1] = bqkv + 3072;
    qc.q[1] = q1; qc.k[1] = k1; qc.v[1] = v1;
    gemm_qkv<<<dim3(12, MROWS / 128), 256, GEMM_SMEM>>>(qc);

    AttA ac;
    ac.Q[0] = q1; ac.K[0] = k1; ac.V[0] = v1; ac.O[0] = ctx1;
    ac.Q[1] = q1; ac.K[1] = k1; ac.V[1] = v1; ac.O[1] = ctx1;
    attn_bf<<<dim3(SEQ / 128, NHEAD, BATCH), 256, ATT_SMEM>>>(ac);

    gemm_bf<1><<<dim3(4, MROWS / 128), 256, GEMM_SMEM>>>(
        ctx1, Wor, bo, nullptr, x1, xres, nullptr, MROWS, DMODEL, DMODEL, 0);

    // final LN + MLP
    LnA lf;
    lf.x[0] = xres; lf.x[1] = xres;
    lf.g[0] = lnf_g; lf.g[1] = lnf_g;
    lf.b[0] = lnf_b; lf.b[1] = lnf_b;
    lf.y[0] = x1n;  lf.y[1] = x1n;
    ln2_kernel<<<MROWS, 128>>>(lf);

    gemm_bf<0><<<dim3(8, MROWS / 128), 256, GEMM_SMEM>>>(
        x1n, W1r, b1, nullptr, nullptr, nullptr, hbuf, MROWS, DMLP, DMODEL, 1);
    gemm_bf<1><<<dim3(4, MROWS / 128), 256, GEMM_SMEM>>>(
        hbuf, W2r, b2, nullptr, xres, out, nullptr, MROWS, DMODEL, DMLP, 0);
}